// round 13
// baseline (speedup 1.0000x reference)
#include <cuda_runtime.h>
#include <cuda_fp16.h>
#include <math.h>

#define TT   365
#define NPTS 400
#define DD   104
#define HH   4
#define HD   26
#define TN   (TT*NPTS)      // 146000
#define D2   (2*DD)         // 208
#define D3   (3*DD)         // 312
#define TD   (TT*DD)        // 37960
#define SPLITK 40
#define KCHUNK 960
#define SMA  40              // A/B smem row stride in halves (32 k + 8 pad)
#define A_STH (128*SMA)
#define B_STH (64*SMA)
#define SMEM_BATCH ((3*A_STH + 3*B_STH)*2)
#define SMEM_STREAM_MAX 61440

// ---------------- scratch (device globals; no runtime allocation) -------------
__device__ __align__(16) __half g_hcat[(size_t)TN*DD];
__device__ __align__(16) __half g_h   [(size_t)TN*DD];
__device__ __align__(16) __half g_hT  [(size_t)TN*DD];   // [T][D][N]
__device__ __align__(16) __half g_graph[(size_t)TT*NPTS*NPTS];
__device__ __align__(16) __half g_z1  [(size_t)TN*DD];
__device__ __align__(16) __half g_qkv [(size_t)TN*D3];
__device__ __align__(16) __half g_qkv2[(size_t)TN*D3];
__device__ float g_kvs_s [(size_t)TT*HH*HD*HD];
__device__ float g_ksum_s[(size_t)TT*HH*HD];
__device__ float g_kvs_t [(size_t)NPTS*HH*HD*HD];
__device__ float g_ksum_t[(size_t)NPTS*HH*HD];
__device__ float g_kvs_s2 [(size_t)TT*HH*HD*HD];
__device__ float g_ksum_s2[(size_t)TT*HH*HD];
__device__ float g_kvs_t2 [(size_t)NPTS*HH*HD*HD];
__device__ float g_ksum_t2[(size_t)NPTS*HH*HD];
__device__ __align__(16) __half g_cat2 [(size_t)TN*D2];
__device__ __align__(16) __half g_cat2b[(size_t)TN*D2];
__device__ __align__(16) __half g_att0[(size_t)TN*DD];
__device__ float  g_att1[(size_t)TN*DD];
__device__ float  g_p0  [(size_t)TN*DD];
__device__ float  g_p1  [(size_t)TN*DD];
__device__ __align__(16) __half g_h1  [(size_t)TN*DD];
__device__ float  g_t2  [(size_t)TN*DD];
__device__ __align__(16) __half g_h2t [(size_t)NPTS*TD];
__device__ float  g_part[(size_t)SPLITK*NPTS*DD];
__device__ __align__(16) __half g_y   [(size_t)NPTS*DD];
__device__ __align__(16) __half g_yh  [(size_t)NPTS*D2];
__device__ __align__(16) __half g_wtsh[(size_t)16000000];

// offsets into g_wtsh (halves)
#define O_ADP   0L
#define O_WTP   11680000L
#define O_QKVW  11690816L
#define O_OPW   11755712L
#define O_PWW   11798976L
#define O_FC1   11820608L
#define O_FC2   11842240L
#define O_EPW   11863872L
#define O_ENC1  15811712L
#define O_ENC2  15876608L
#define O_OUTW  15941504L

// ---------------- cp.async issue helpers ----------------------------------------
__device__ __forceinline__ void issue_a(const __half* __restrict__ A, unsigned sAs,
                                        int bm, int k0, int kend, int M, long K, int tid)
{
    #pragma unroll
    for (int p = 0; p < 2; p++) {
        int idx = tid + p * 256;
        int m = idx >> 2, kq = (idx & 3) << 3;
        int gm = bm + m;
        int rem = kend - (k0 + kq);
        int sz = (gm < M && rem >= 8) ? 16 : 0;
        const __half* src = sz ? A + (long)gm * K + k0 + kq : A;
        unsigned dst = sAs + (unsigned)(m * SMA + kq) * 2u;
        asm volatile("cp.async.ca.shared.global [%0],[%1],16,%2;"
                     :: "r"(dst), "l"(src), "r"(sz));
    }
}

__device__ __forceinline__ void issue_b(const __half* __restrict__ B, unsigned sBs,
                                        int bn, int k0, int kend, int Nc, long K, int tid)
{
    int n = tid >> 2, kq = (tid & 3) << 3;
    int gn = bn + n;
    int rem = kend - (k0 + kq);
    int sz = (gn < Nc && rem >= 8) ? 16 : 0;
    const __half* src = sz ? B + (long)gn * K + k0 + kq : B;
    unsigned dst = sBs + (unsigned)(n * SMA + kq) * 2u;
    asm volatile("cp.async.ca.shared.global [%0],[%1],16,%2;"
                 :: "r"(dst), "l"(src), "r"(sz));
}

// ---------------- fp16 MMA on a k32 chunk ---------------------------------------
__device__ __forceinline__ void mma_chunk(const __half* __restrict__ As, int sbA,
                                          const __half* __restrict__ Bs, int sbB,
                                          int wm, int wn, int lane, float (*acc)[4][4])
{
    int r = lane >> 2, c2 = (lane & 3) << 1;
    #pragma unroll
    for (int ks = 0; ks < 2; ks++) {
        int k0 = ks * 16;
        unsigned a[2][4], b[4][2];
        #pragma unroll
        for (int mt = 0; mt < 2; mt++) {
            const __half* p = As + (wm * 32 + mt * 16 + r) * sbA + k0 + c2;
            a[mt][0] = *reinterpret_cast<const unsigned*>(p);
            a[mt][1] = *reinterpret_cast<const unsigned*>(p + 8 * sbA);
            a[mt][2] = *reinterpret_cast<const unsigned*>(p + 8);
            a[mt][3] = *reinterpret_cast<const unsigned*>(p + 8 * sbA + 8);
        }
        #pragma unroll
        for (int nt = 0; nt < 4; nt++) {
            const __half* q = Bs + (wn * 32 + nt * 8 + r) * sbB + k0 + c2;
            b[nt][0] = *reinterpret_cast<const unsigned*>(q);
            b[nt][1] = *reinterpret_cast<const unsigned*>(q + 8);
        }
        #pragma unroll
        for (int mt = 0; mt < 2; mt++)
            #pragma unroll
            for (int nt = 0; nt < 4; nt++)
                asm("mma.sync.aligned.m16n8k16.row.col.f32.f16.f16.f32 "
                    "{%0,%1,%2,%3},{%4,%5,%6,%7},{%8,%9},{%0,%1,%2,%3};"
                    : "+f"(acc[mt][nt][0]), "+f"(acc[mt][nt][1]),
                      "+f"(acc[mt][nt][2]), "+f"(acc[mt][nt][3])
                    : "r"(a[mt][0]), "r"(a[mt][1]), "r"(a[mt][2]), "r"(a[mt][3]),
                      "r"(b[nt][0]), "r"(b[nt][1]));
    }
}

// ---------------- epilogue -------------------------------------------------------
template<bool RELU, bool ACC, bool SPLIT, typename TC>
__device__ __forceinline__ void epilogue(float (*acc)[4][4], const float* bias,
                                         TC* __restrict__ C, int bm, int bn,
                                         int M, int Nc, int wm, int wn, int lane)
{
    int r = lane >> 2, c2 = (lane & 3) << 1;
    #pragma unroll
    for (int mt = 0; mt < 2; mt++) {
        #pragma unroll
        for (int nt = 0; nt < 4; nt++) {
            int gm0 = bm + wm * 32 + mt * 16 + r;
            int gn0 = bn + wn * 32 + nt * 8 + c2;
            #pragma unroll
            for (int hh = 0; hh < 2; hh++) {
                int gm = gm0 + hh * 8;
                if (gm >= M) continue;
                #pragma unroll
                for (int j = 0; j < 2; j++) {
                    int gn = gn0 + j;
                    if (gn >= Nc) continue;
                    float v = acc[mt][nt][hh * 2 + j];
                    if (!SPLIT && bias) v += bias[gn];
                    if (RELU) v = fmaxf(v, 0.f);
                    long ci = (long)gm * Nc + gn;
                    if (ACC) v += (float)C[ci];
                    C[ci] = (TC)v;
                }
            }
        }
    }
}

// ---------------- batched / split fp16 GEMM (B always [n][k]) -------------------
template<bool SPLIT, typename TC>
__global__ void __launch_bounds__(256)
gemm_kernel(const __half* __restrict__ A, const __half* __restrict__ B,
            const float* __restrict__ bias, TC* __restrict__ C,
            int M, int K, int Nc, long sA, long sB_, long sC)
{
    extern __shared__ __half dsmh[];
    int tid = threadIdx.x;
    int bm = blockIdx.y * 128, bn = blockIdx.x * 64;
    int kbeg = 0, kend = K;
    if (SPLIT) {
        int z = blockIdx.z;
        kbeg = z * KCHUNK;
        kend = min(K, kbeg + KCHUNK);
        C += (long)z * M * Nc;
    } else {
        int z = blockIdx.z;
        A += z * sA; B += z * sB_; C += z * sC;
    }
    int w = tid >> 5, lane = tid & 31;
    int wm = w >> 1, wn = w & 1;
    float acc[2][4][4];
    #pragma unroll
    for (int mt = 0; mt < 2; mt++)
        #pragma unroll
        for (int nt = 0; nt < 4; nt++)
            #pragma unroll
            for (int q = 0; q < 4; q++) acc[mt][nt][q] = 0.f;

    unsigned sbase = (unsigned)__cvta_generic_to_shared(dsmh);
    unsigned sA0 = sbase;
    unsigned sB0 = sbase + 3u * A_STH * 2u;

    int nk = (kend - kbeg + 31) >> 5;
    issue_a(A, sA0, bm, kbeg, kend, M, K, tid);
    issue_b(B, sB0, bn, kbeg, kend, Nc, K, tid);
    asm volatile("cp.async.commit_group;" ::: "memory");
    issue_a(A, sA0 + A_STH * 2u, bm, kbeg + 32, kend, M, K, tid);
    issue_b(B, sB0 + B_STH * 2u, bn, kbeg + 32, kend, Nc, K, tid);
    asm volatile("cp.async.commit_group;" ::: "memory");

    for (int it = 0; it < nk; it++) {
        asm volatile("cp.async.wait_group 1;" ::: "memory");
        __syncthreads();
        int s2 = (it + 2) % 3;
        int kn = kbeg + (it + 2) * 32;
        issue_a(A, sA0 + (unsigned)s2 * A_STH * 2u, bm, kn, kend, M, K, tid);
        issue_b(B, sB0 + (unsigned)s2 * B_STH * 2u, bn, kn, kend, Nc, K, tid);
        asm volatile("cp.async.commit_group;" ::: "memory");
        int sc = it % 3;
        mma_chunk(dsmh + sc * A_STH, SMA, dsmh + 3 * A_STH + sc * B_STH, SMA,
                  wm, wn, lane, acc);
    }
    epilogue<false, false, SPLIT, TC>(acc, bias, C, bm, bn, M, Nc, wm, wn, lane);
}

// ---------------- persistent-B streaming GEMM (NN, non-batched) -----------------
template<bool RELU, bool ACC, typename TC>
__global__ void __launch_bounds__(256)
gemm_stream(const __half* __restrict__ A, const __half* __restrict__ Bt,
            const float* __restrict__ bias, TC* __restrict__ C,
            int M, int K, int Nc, int KP)
{
    extern __shared__ __half dsmh[];
    __half* Asm = dsmh;
    __half* Bsm = dsmh + 3 * A_STH;
    int tid = threadIdx.x;
    int bn = blockIdx.x * 64;
    int nkc = (K + 31) >> 5;
    int KP32 = nkc * 32;
    int MT = (M + 127) >> 7;
    int w = tid >> 5, lane = tid & 31;
    int wm = w >> 1, wn = w & 1;

    unsigned sbase = (unsigned)__cvta_generic_to_shared(dsmh);
    unsigned sA0 = sbase;
    unsigned sB0 = sbase + 3u * A_STH * 2u;

    int nchunk = KP32 >> 3;
    for (int e = tid; e < 64 * nchunk; e += 256) {
        int n = e / nchunk, kc8 = e - n * nchunk;
        int k = kc8 << 3;
        int gn = bn + n;
        int sz = (gn < Nc && k < K) ? 16 : 0;
        const __half* src = sz ? Bt + (long)gn * K + k : Bt;
        unsigned dst = sB0 + (unsigned)(n * KP + k) * 2u;
        asm volatile("cp.async.ca.shared.global [%0],[%1],16,%2;"
                     :: "r"(dst), "l"(src), "r"(sz));
    }

    int mt_i = blockIdx.y;
    int kc_i = 0;
    if (mt_i < MT) issue_a(A, sA0, mt_i * 128, 0, K, M, K, tid);
    asm volatile("cp.async.commit_group;" ::: "memory");
    if (++kc_i == nkc) { kc_i = 0; mt_i += gridDim.y; }
    if (mt_i < MT) issue_a(A, sA0 + A_STH * 2u, mt_i * 128, kc_i * 32, K, M, K, tid);
    asm volatile("cp.async.commit_group;" ::: "memory");
    if (++kc_i == nkc) { kc_i = 0; mt_i += gridDim.y; }

    float acc[2][4][4];
    int stage = 0;
    for (int mt = blockIdx.y; mt < MT; mt += gridDim.y) {
        #pragma unroll
        for (int mtt = 0; mtt < 2; mtt++)
            #pragma unroll
            for (int nt = 0; nt < 4; nt++)
                #pragma unroll
                for (int q = 0; q < 4; q++) acc[mtt][nt][q] = 0.f;
        for (int kc = 0; kc < nkc; kc++) {
            asm volatile("cp.async.wait_group 1;" ::: "memory");
            __syncthreads();
            int s2 = (stage + 2) % 3;
            if (mt_i < MT) issue_a(A, sA0 + (unsigned)s2 * A_STH * 2u,
                                   mt_i * 128, kc_i * 32, K, M, K, tid);
            asm volatile("cp.async.commit_group;" ::: "memory");
            if (++kc_i == nkc) { kc_i = 0; mt_i += gridDim.y; }
            mma_chunk(Asm + stage * A_STH, SMA, Bsm + kc * 32, KP, wm, wn, lane, acc);
            stage = (stage + 1) % 3;
        }
        epilogue<RELU, ACC, false, TC>(acc, bias, C, mt * 128, bn, M, Nc, wm, wn, lane);
    }
}

// ---------------- fused relu-softmax normalize (fp16 in/out) --------------------
__global__ void normgraph_kernel(__half* __restrict__ g)
{
    long row = (long)blockIdx.x * 8 + (threadIdx.x >> 5);
    if (row >= (long)TN) return;
    int lane = threadIdx.x & 31;
    uint4* p = reinterpret_cast<uint4*>(g + row * NPTS);
    float v[2][8]; uint4 u;
    float m = 0.f;
    #pragma unroll
    for (int rch = 0; rch < 2; rch++) {
        int c = lane + rch * 32;
        if (c < 50) {
            u = p[c];
            const __half2* hp = reinterpret_cast<const __half2*>(&u);
            #pragma unroll
            for (int j = 0; j < 4; j++) {
                float2 f = __half22float2(hp[j]);
                v[rch][2 * j] = f.x; v[rch][2 * j + 1] = f.y;
                m = fmaxf(m, fmaxf(f.x, f.y));
            }
        }
    }
    #pragma unroll
    for (int o = 16; o > 0; o >>= 1) m = fmaxf(m, __shfl_xor_sync(~0u, m, o));
    float s = 0.f;
    #pragma unroll
    for (int rch = 0; rch < 2; rch++) {
        int c = lane + rch * 32;
        if (c < 50) {
            #pragma unroll
            for (int j = 0; j < 8; j++) {
                float e = __expf(fmaxf(v[rch][j], 0.f) - m);
                v[rch][j] = e; s += e;
            }
        }
    }
    #pragma unroll
    for (int o = 16; o > 0; o >>= 1) s += __shfl_xor_sync(~0u, s, o);
    float inv = 1.f / s;
    #pragma unroll
    for (int rch = 0; rch < 2; rch++) {
        int c = lane + rch * 32;
        if (c < 50) {
            uint4 ou;
            __half2* hp = reinterpret_cast<__half2*>(&ou);
            #pragma unroll
            for (int j = 0; j < 4; j++)
                hp[j] = __floats2half2_rn(v[rch][2 * j] * inv, v[rch][2 * j + 1] * inv);
            p[c] = ou;
        }
    }
}

// ---------------- weight conversion kernels -------------------------------------
__global__ void rnd2h_kernel(const float* __restrict__ src, __half* __restrict__ dst, long n2)
{
    long i = (long)blockIdx.x * 256 + threadIdx.x;
    if (i >= n2) return;
    float2 f = reinterpret_cast<const float2*>(src)[i];
    reinterpret_cast<__half2*>(dst)[i] = __floats2half2_rn(f.x, f.y);
}

__global__ void trnd_kernel(const float* __restrict__ src, __half* __restrict__ dst,
                            int K, int Nc)
{
    long j = (long)blockIdx.x * 256 + threadIdx.x;
    if (j >= (long)K * Nc) return;
    int n = (int)(j / K); long k = j - (long)n * K;
    dst[j] = __float2half_rn(src[k * Nc + n]);
}

__global__ void trnd_tiled_kernel(const float* __restrict__ src, __half* __restrict__ dst,
                                  int K, int Nc)
{
    __shared__ float tile[32][33];
    int k0 = blockIdx.x * 32, n0 = blockIdx.y * 32;
    int tx = threadIdx.x & 31, ty = threadIdx.x >> 5;
    #pragma unroll
    for (int i = ty; i < 32; i += 8) {
        int k = k0 + i, n = n0 + tx;
        tile[i][tx] = (k < K && n < Nc) ? src[(long)k * Nc + n] : 0.f;
    }
    __syncthreads();
    #pragma unroll
    for (int i = ty; i < 32; i += 8) {
        int n = n0 + i, k = k0 + tx;
        if (n < Nc && k < K) dst[(long)n * K + k] = __float2half_rn(tile[tx][i]);
    }
}

// ---------------- input proj + concat adaptive embedding ------------------------
__global__ void hcat_kernel(const float* __restrict__ x, const float* __restrict__ W_in,
                            const float* __restrict__ b_in, const __half* __restrict__ adp_h,
                            __half* __restrict__ hcat)
{
    long idx = (long)blockIdx.x * 256 + threadIdx.x;
    if (idx >= (long)TN * DD) return;
    long tn = idx / DD; int j = (int)(idx - tn * DD);
    int t = (int)(tn / NPTS), n = (int)(tn - (long)t * NPTS);
    __half v;
    if (j < 24) {
        const float* xr = x + ((long)n * TT + t) * 3;
        v = __float2half_rn(b_in[j] + xr[0] * W_in[0 * 24 + j]
                            + xr[1] * W_in[1 * 24 + j] + xr[2] * W_in[2 * 24 + j]);
    } else {
        v = adp_h[tn * 80 + (j - 24)];
    }
    hcat[idx] = v;
}

// ---------------- h -> hT [T][D][N] ----------------------------------------------
__global__ void transpose_hT_kernel(const __half* __restrict__ h, __half* __restrict__ hT)
{
    long idx = (long)blockIdx.x * 256 + threadIdx.x;
    if (idx >= (long)TN * DD) return;
    long t = idx / ((long)NPTS * DD);
    long r = idx - t * ((long)NPTS * DD);
    long n = r / DD;
    long d = r - n * DD;
    hT[t * (long)DD * NPTS + d * NPTS + n] = h[idx];
}

// ---------------- linear attention: kvs + ksum ----------------------------------
__global__ void kvs_kernel(const __half* __restrict__ qkv, long sB, long sL, int L,
                           float* __restrict__ kvs, float* __restrict__ ksum)
{
    int b = blockIdx.x, h = blockIdx.y;
    int w = threadIdx.x >> 5, lane = threadIdx.x & 31;
    int chunk = (L + 7) >> 3;
    int l0 = w * chunk, l1 = min(L, l0 + chunk);
    const __half* base = qkv + (long)b * sB + h * HD;
    float acc[HD];
    #pragma unroll
    for (int m = 0; m < HD; m++) acc[m] = 0.f;
    float accs = 0.f;
    for (int l = l0; l < l1; l++) {
        const __half* row = base + (long)l * sL;
        float kk = (lane < HD) ? __half2float(row[DD + lane]) : 0.f;
        float vv = (lane < HD) ? __half2float(row[2 * DD + lane]) : 0.f;
        float ss = kk * kk;
        #pragma unroll
        for (int o = 16; o > 0; o >>= 1) ss += __shfl_xor_sync(~0u, ss, o);
        float inv = 1.f / fmaxf(sqrtf(ss), 1e-12f);
        float kin = kk * inv;
        accs += kin;
        #pragma unroll
        for (int m = 0; m < HD; m++) {
            float km = __shfl_sync(~0u, kin, m);
            acc[m] += km * vv;
        }
    }
    __shared__ float red[8][HD][HD + 2];
    __shared__ float redk[8][32];
    if (lane < HD) {
        #pragma unroll
        for (int m = 0; m < HD; m++) red[w][m][lane] = acc[m];
    }
    redk[w][lane] = accs;
    __syncthreads();
    long basec = ((long)b * HH + h);
    for (int cell = threadIdx.x; cell < HD * HD; cell += 256) {
        int m = cell / HD, d = cell - m * HD;
        float s = 0.f;
        #pragma unroll
        for (int ww = 0; ww < 8; ww++) s += red[ww][m][d];
        kvs[basec * (HD * HD) + cell] = s;
    }
    if (threadIdx.x < HD) {
        float s = 0.f;
        #pragma unroll
        for (int ww = 0; ww < 8; ww++) s += redk[ww][threadIdx.x];
        ksum[basec * HD + threadIdx.x] = s;
    }
}

// ---------------- attention output, tiled: one kv-owner x 16-token slice --------
// grid = (ceil(ninner/16), nouter); 512 threads process 4 tokens/iter, 4 iters.
__global__ void __launch_bounds__(512)
attnout_tile_kernel(const __half* __restrict__ qkv, const float* __restrict__ kvs,
                    const float* __restrict__ ksum, __half* __restrict__ cat2,
                    int ninner, long strideOuter, long strideInner, float Lc, int ooff)
{
    __shared__ float skvs[HH][HD][HD + 1];
    __shared__ float sksum[HH][HD];
    __shared__ float sq[4][DD], sv[4][DD];
    __shared__ float sinv[4][HH], sden[4][HH];
    int tid = threadIdx.x;
    int g = tid >> 7, gt = tid & 127;
    long base = (long)blockIdx.y;
    int i0 = blockIdx.x * 16;
    for (int i = tid; i < HH * HD * HD; i += 512) {
        int h = i / (HD * HD); int r = i - h * (HD * HD);
        skvs[h][r / HD][r % HD] = kvs[(base * HH + h) * (HD * HD) + r];
    }
    for (int i = tid; i < HH * HD; i += 512)
        sksum[i / HD][i % HD] = ksum[base * HH * HD + i];
    __syncthreads();
    #pragma unroll
    for (int it = 0; it < 4; it++) {
        int i = i0 + it * 4 + g;
        bool act = (i < ninner);
        long tok = base * strideOuter + (long)i * strideInner;
        if (act && gt < DD) {
            const __half* row = qkv + tok * D3;
            sq[g][gt] = __half2float(row[gt]);
            sv[g][gt] = __half2float(row[2 * DD + gt]);
        }
        __syncthreads();
        if (act && gt < HH) {
            const float* qh = sq[g] + gt * HD;
            float ss = 0.f;
            #pragma unroll
            for (int m = 0; m < HD; m++) ss += qh[m] * qh[m];
            float inv = 1.f / fmaxf(sqrtf(ss), 1e-12f);
            sinv[g][gt] = inv;
            float dd = 0.f;
            #pragma unroll
            for (int m = 0; m < HD; m++) dd += qh[m] * sksum[gt][m];
            sden[g][gt] = dd * inv + Lc;
        }
        __syncthreads();
        if (act && gt < DD) {
            int h = gt / HD, d = gt - h * HD;
            const float* qh = sq[g] + h * HD;
            float s = 0.f;
            #pragma unroll
            for (int m = 0; m < HD; m++) s += qh[m] * skvs[h][m][d];
            float num = s * sinv[g][h] + Lc * sv[g][gt];
            cat2[tok * D2 + ooff + gt] = __float2half_rn(num / sden[g][h]);
        }
        __syncthreads();
    }
}

// ---------------- fused combine + LayerNorm --------------------------------------
__global__ void combine_ln_kernel(const __half* __restrict__ h, const __half* __restrict__ a0,
                                  const float* __restrict__ a1, const float* __restrict__ p0,
                                  const float* __restrict__ p1, const float* __restrict__ gam,
                                  const float* __restrict__ bet, __half* __restrict__ out)
{
    long row = blockIdx.x; int tid = threadIdx.x;
    __shared__ float red[4];
    long i = row * DD + tid;
    float v = 0.f;
    if (tid < DD)
        v = 2.f * (__half2float(h[i]) + __half2float(a0[i]) * p0[i] + 0.01f * a1[i] * p1[i]);
    float s = (tid < DD) ? v : 0.f;
    #pragma unroll
    for (int o = 16; o > 0; o >>= 1) s += __shfl_xor_sync(~0u, s, o);
    if ((tid & 31) == 0) red[tid >> 5] = s;
    __syncthreads();
    float mean = (red[0] + red[1] + red[2] + red[3]) / (float)DD;
    __syncthreads();
    float d = (tid < DD) ? (v - mean) : 0.f;
    float s2 = d * d;
    #pragma unroll
    for (int o = 16; o > 0; o >>= 1) s2 += __shfl_xor_sync(~0u, s2, o);
    if ((tid & 31) == 0) red[tid >> 5] = s2;
    __syncthreads();
    float var = (red[0] + red[1] + red[2] + red[3]) / (float)DD;
    if (tid < DD) out[i] = __float2half_rn(d * rsqrtf(var + 1e-5f) * gam[tid] + bet[tid]);
}

// ln + residual, writing DIRECTLY into transposed layout h2t[n][t*DD+d]
__global__ void ln_res_t_kernel(const __half* __restrict__ a, const float* __restrict__ b,
                                const float* __restrict__ gam, const float* __restrict__ bet,
                                __half* __restrict__ h2t)
{
    long row = blockIdx.x; int tid = threadIdx.x;
    __shared__ float red[4];
    long i = row * DD + tid;
    float v = 0.f;
    if (tid < DD) v = __half2float(a[i]) + b[i];
    float s = (tid < DD) ? v : 0.f;
    #pragma unroll
    for (int o = 16; o > 0; o >>= 1) s += __shfl_xor_sync(~0u, s, o);
    if ((tid & 31) == 0) red[tid >> 5] = s;
    __syncthreads();
    float mean = (red[0] + red[1] + red[2] + red[3]) / (float)DD;
    __syncthreads();
    float d = (tid < DD) ? (v - mean) : 0.f;
    float s2 = d * d;
    #pragma unroll
    for (int o = 16; o > 0; o >>= 1) s2 += __shfl_xor_sync(~0u, s2, o);
    if ((tid & 31) == 0) red[tid >> 5] = s2;
    __syncthreads();
    float var = (red[0] + red[1] + red[2] + red[3]) / (float)DD;
    if (tid < DD) {
        long t = row / NPTS, n = row - t * NPTS;
        h2t[n * (long)TD + t * DD + tid] =
            __float2half_rn(d * rsqrtf(var + 1e-5f) * gam[tid] + bet[tid]);
    }
}

// ---------------- split-K deterministic reduction -------------------------------
__global__ void splitk_reduce_kernel(const float* __restrict__ part, const float* __restrict__ bias,
                                     __half* __restrict__ y, int MN, int Z, int Nc)
{
    int i = blockIdx.x * 256 + threadIdx.x;
    if (i >= MN) return;
    float s = bias[i % Nc];
    for (int z = 0; z < Z; z++) s += part[(long)z * MN + i];
    y[i] = __float2half_rn(s);
}

// ---------------- streaming GEMM launcher ---------------------------------------
template<bool RELU, bool ACC, typename TC>
static void launch_stream_t(const __half* A, const __half* Bt, const float* bias, TC* C,
                            int M, int K, int Nc, cudaStream_t st)
{
    int nkc = (K + 31) / 32;
    int KP = nkc * 32 + 8;
    int smem = 3 * A_STH * 2 + 64 * KP * 2;
    int nx = (Nc + 63) / 64;
    int MT = (M + 127) / 128;
    int gy = (444 + nx - 1) / nx;
    if (gy > MT) gy = MT;
    gemm_stream<RELU, ACC, TC><<<dim3(nx, gy), 256, smem, st>>>(A, Bt, bias, C, M, K, Nc, KP);
}

// ---------------- host orchestration --------------------------------------------
static void run_attention(const __half* x4, const __half* qwT, const __half* owT,
                          const float* ob, __half* qkv,
                          float* kvs_s, float* ksum_s, float* kvs_t, float* ksum_t,
                          __half* cat2, __half* att_h, float* att_f, cudaStream_t st)
{
    launch_stream_t<false, false, __half>(x4, qwT, nullptr, qkv, TN, DD, D3, st);
    kvs_kernel<<<dim3(TT, HH), 256, 0, st>>>(qkv, (long)NPTS * D3, (long)D3, NPTS, kvs_s, ksum_s);
    kvs_kernel<<<dim3(NPTS, HH), 256, 0, st>>>(qkv, (long)D3, (long)NPTS * D3, TT, kvs_t, ksum_t);
    // spatial: outer=t, inner=n (16-token tiles); temporal: outer=n, inner=t
    attnout_tile_kernel<<<dim3((NPTS + 15) / 16, TT), 512, 0, st>>>(
        qkv, kvs_s, ksum_s, cat2, NPTS, (long)NPTS, 1L, (float)NPTS, 0);
    attnout_tile_kernel<<<dim3((TT + 15) / 16, NPTS), 512, 0, st>>>(
        qkv, kvs_t, ksum_t, cat2, TT, 1L, (long)NPTS, (float)TT, DD);
    if (att_h) launch_stream_t<false, false, __half>(cat2, owT, ob, att_h, TN, D2, DD, st);
    else       launch_stream_t<false, false, float >(cat2, owT, ob, att_f, TN, D2, DD, st);
}

extern "C" void kernel_launch(void* const* d_in, const int* in_sizes, int n_in,
                              void* d_out, int out_size)
{
    (void)in_sizes; (void)n_in; (void)out_size;
    const float* x     = (const float*)d_in[0];
    const float* W_in  = (const float*)d_in[1];
    const float* b_in  = (const float*)d_in[2];
    const float* adp   = (const float*)d_in[3];
    const float* W_tp  = (const float*)d_in[4];
    const float* b_tp  = (const float*)d_in[5];
    const float* qkv_w = (const float*)d_in[6];
    const float* op_w  = (const float*)d_in[7];
    const float* op_b  = (const float*)d_in[8];
    const float* pw_w  = (const float*)d_in[9];
    const float* pw_b  = (const float*)d_in[10];
    const float* fc_w1 = (const float*)d_in[11];
    const float* fc_b1 = (const float*)d_in[12];
    const float* fc_w2 = (const float*)d_in[13];
    const float* fc_b2 = (const float*)d_in[14];
    const float* ln1_g = (const float*)d_in[15];
    const float* ln1_b = (const float*)d_in[16];
    const float* ln2_g = (const float*)d_in[17];
    const float* ln2_b = (const float*)d_in[18];
    const float* ep_w  = (const float*)d_in[19];
    const float* ep_b  = (const float*)d_in[20];
    const float* enc_w1= (const float*)d_in[21];
    const float* enc_b1= (const float*)d_in[22];
    const float* enc_w2= (const float*)d_in[23];
    const float* enc_b2= (const float*)d_in[24];
    const float* out_w = (const float*)d_in[25];
    const float* out_b = (const float*)d_in[26];
    float* out = (float*)d_out;

    static cudaStream_t s1 = nullptr;
    static cudaEvent_t evAdp, evHT, evB1;
    if (!s1) {
        cudaStreamCreateWithFlags(&s1, cudaStreamNonBlocking);
        cudaEventCreateWithFlags(&evAdp, cudaEventDisableTiming);
        cudaEventCreateWithFlags(&evHT,  cudaEventDisableTiming);
        cudaEventCreateWithFlags(&evB1,  cudaEventDisableTiming);
        cudaFuncSetAttribute(gemm_kernel<false, __half>,
                             cudaFuncAttributeMaxDynamicSharedMemorySize, SMEM_BATCH);
        cudaFuncSetAttribute(gemm_kernel<true, float>,
                             cudaFuncAttributeMaxDynamicSharedMemorySize, SMEM_BATCH);
        cudaFuncSetAttribute(gemm_stream<false, false, __half>,
                             cudaFuncAttributeMaxDynamicSharedMemorySize, SMEM_STREAM_MAX);
        cudaFuncSetAttribute(gemm_stream<true, false, __half>,
                             cudaFuncAttributeMaxDynamicSharedMemorySize, SMEM_STREAM_MAX);
        cudaFuncSetAttribute(gemm_stream<false, true, __half>,
                             cudaFuncAttributeMaxDynamicSharedMemorySize, SMEM_STREAM_MAX);
        cudaFuncSetAttribute(gemm_stream<false, false, float>,
                             cudaFuncAttributeMaxDynamicSharedMemorySize, SMEM_STREAM_MAX);
    }

    __half *hcat, *h, *hT, *graph, *z1, *qkv, *qkv2, *cat2, *cat2b, *att0;
    __half *h1, *h2t, *y, *yh, *wtsh;
    float *kvs_s, *ksum_s, *kvs_t, *ksum_t, *kvs_s2, *ksum_s2, *kvs_t2, *ksum_t2;
    float *att1, *p0, *p1, *t2, *part;
    cudaGetSymbolAddress((void**)&hcat, g_hcat);
    cudaGetSymbolAddress((void**)&h,    g_h);
    cudaGetSymbolAddress((void**)&hT,   g_hT);
    cudaGetSymbolAddress((void**)&graph,g_graph);
    cudaGetSymbolAddress((void**)&z1,   g_z1);
    cudaGetSymbolAddress((void**)&qkv,  g_qkv);
    cudaGetSymbolAddress((void**)&qkv2, g_qkv2);
    cudaGetSymbolAddress((void**)&kvs_s,  g_kvs_s);
    cudaGetSymbolAddress((void**)&ksum_s, g_ksum_s);
    cudaGetSymbolAddress((void**)&kvs_t,  g_kvs_t);
    cudaGetSymbolAddress((void**)&ksum_t, g_ksum_t);
    cudaGetSymbolAddress((void**)&kvs_s2, g_kvs_s2);
    cudaGetSymbolAddress((void**)&ksum_s2,g_ksum_s2);
    cudaGetSymbolAddress((void**)&kvs_t2, g_kvs_t2);
    cudaGetSymbolAddress((void**)&ksum_t2,g_ksum_t2);
    cudaGetSymbolAddress((void**)&cat2,  g_cat2);
    cudaGetSymbolAddress((void**)&cat2b, g_cat2b);
    cudaGetSymbolAddress((void**)&att0, g_att0);
    cudaGetSymbolAddress((void**)&att1, g_att1);
    cudaGetSymbolAddress((void**)&p0,   g_p0);
    cudaGetSymbolAddress((void**)&p1,   g_p1);
    cudaGetSymbolAddress((void**)&h1,   g_h1);
    cudaGetSymbolAddress((void**)&t2,   g_t2);
    cudaGetSymbolAddress((void**)&h2t,  g_h2t);
    cudaGetSymbolAddress((void**)&part, g_part);
    cudaGetSymbolAddress((void**)&y,    g_y);
    cudaGetSymbolAddress((void**)&yh,   g_yh);
    cudaGetSymbolAddress((void**)&wtsh, g_wtsh);

    __half* adp_h  = wtsh + O_ADP;
    __half* WtpT   = wtsh + O_WTP;
    __half* qkvwT  = wtsh + O_QKVW;
    __half* opwT   = wtsh + O_OPW;
    __half* pwwT   = wtsh + O_PWW;
    __half* fc1T   = wtsh + O_FC1;
    __half* fc2T   = wtsh + O_FC2;
    __half* epwT   = wtsh + O_EPW;
    __half* enc1T  = wtsh + O_ENC1;
    __half* enc2T  = wtsh + O_ENC2;
    __half* outwT  = wtsh + O_OUTW;

    {
        long n2 = (long)TT * NPTS * 80 / 2;
        rnd2h_kernel<<<(n2 + 255) / 256, 256>>>(adp, adp_h, n2);
    }

    // ======== FORK: graph branch on s1 ========
    cudaEventRecord(evAdp, 0);
    cudaStreamWaitEvent(s1, evAdp, 0);
    gemm_kernel<false, __half><<<dim3(7, 4, TT), 256, SMEM_BATCH, s1>>>(
        adp_h, adp_h, nullptr, graph, NPTS, 80, NPTS,
        (long)NPTS * 80, (long)NPTS * 80, (long)NPTS * NPTS);
    normgraph_kernel<<<(TN + 7) / 8, 256, 0, s1>>>(graph);

    #define TRND(src, dst, K_, N_) \
        trnd_kernel<<<(((long)(K_) * (N_)) + 255) / 256, 256>>>(src, dst, K_, N_)
    TRND(W_tp, WtpT, DD, DD);
    TRND(qkv_w,            qkvwT,             DD, D3);
    TRND(qkv_w + DD * D3,  qkvwT + D3 * DD,   DD, D3);
    TRND(op_w,             opwT,              D2, DD);
    TRND(op_w + D2 * DD,   opwT + DD * D2,    D2, DD);
    TRND(pw_w,             pwwT,              DD, DD);
    TRND(pw_w + DD * DD,   pwwT + DD * DD,    DD, DD);
    TRND(fc_w1, fc1T, DD, D2);
    TRND(fc_w2, fc2T, D2, DD);
    for (int i = 0; i < 3; i++) {
        TRND(enc_w1 + (long)i * DD * D2, enc1T + (long)i * D2 * DD, DD, D2);
        TRND(enc_w2 + (long)i * D2 * DD, enc2T + (long)i * DD * D2, D2, DD);
    }
    TRND(out_w, outwT, DD, TT);
    trnd_tiled_kernel<<<dim3((TD + 31) / 32, (DD + 31) / 32), 256>>>(ep_w, epwT, TD, DD);

    // ---- main: h chain ----
    hcat_kernel<<<((long)TN * DD + 255) / 256, 256>>>(x, W_in, b_in, adp_h, hcat);
    launch_stream_t<false, false, __half>(hcat, WtpT, b_tp, h, TN, DD, DD, 0);
    transpose_hT_kernel<<<((long)TN * DD + 255) / 256, 256>>>(h, hT);
    cudaEventRecord(evHT, 0);

    // ======== s1: z1 + attention branch 1 ========
    cudaStreamWaitEvent(s1, evHT, 0);
    gemm_kernel<false, __half><<<dim3(2, 4, TT), 256, SMEM_BATCH, s1>>>(
        graph, hT, nullptr, z1, NPTS, NPTS, DD,
        (long)NPTS * NPTS, (long)DD * NPTS, (long)NPTS * DD);
    run_attention(z1, qkvwT + D3 * DD, opwT + DD * D2, op_b + DD, qkv2,
                  kvs_s2, ksum_s2, kvs_t2, ksum_t2, cat2b, nullptr, att1, s1);
    cudaEventRecord(evB1, s1);

    // ---- main (concurrent): p0, attention branch 0, p1 ----
    launch_stream_t<false, false, float>(h, pwwT, pw_b, p0, TN, DD, DD, 0);
    run_attention(h, qkvwT, opwT, op_b, qkv, kvs_s, ksum_s, kvs_t, ksum_t,
                  cat2, att0, nullptr, 0);
    launch_stream_t<false, false, float>(att0, pwwT + DD * DD, pw_b + DD, p1, TN, DD, DD, 0);

    // ======== JOIN ========
    cudaStreamWaitEvent(0, evB1, 0);

    combine_ln_kernel<<<TN, 128>>>(h, att0, att1, p0, p1, ln1_g, ln1_b, h1);
    launch_stream_t<true,  false, __half>(h1,   fc1T, fc_b1, cat2, TN, DD, D2, 0);
    launch_stream_t<false, false, float >(cat2, fc2T, fc_b2, t2,   TN, D2, DD, 0);
    ln_res_t_kernel<<<TN, 128>>>(h1, t2, ln2_g, ln2_b, h2t);
    gemm_kernel<true, float><<<dim3(2, 4, SPLITK), 256, SMEM_BATCH>>>(
        h2t, epwT, nullptr, part, NPTS, TD, DD, 0, 0, 0);
    splitk_reduce_kernel<<<(NPTS * DD + 255) / 256, 256>>>(part, ep_b, y, NPTS * DD, SPLITK, DD);
    for (int i = 0; i < 3; i++) {
        launch_stream_t<true,  false, __half>(y,  enc1T + (long)i * D2 * DD,
                                              enc_b1 + (long)i * D2, yh, NPTS, DD, D2, 0);
        launch_stream_t<false, true,  __half>(yh, enc2T + (long)i * DD * D2,
                                              enc_b2 + (long)i * DD, y,  NPTS, D2, DD, 0);
    }
    launch_stream_t<false, false, float>(y, outwT, out_b, out, NPTS, DD, TT, 0);
}

// round 14
// speedup vs baseline: 1.2482x; 1.2482x over previous
#include <cuda_runtime.h>
#include <cuda_fp16.h>
#include <math.h>

#define TT   365
#define NPTS 400
#define DD   104
#define HH   4
#define HD   26
#define TN   (TT*NPTS)      // 146000
#define D2   (2*DD)         // 208
#define D3   (3*DD)         // 312
#define TD   (TT*DD)        // 37960
#define SPLITK 40
#define KCHUNK 960
#define SMA  40              // A/B smem row stride in halves (32 k + 8 pad)
#define A_STH (128*SMA)
#define B_STH (64*SMA)
#define SMEM_BATCH ((3*A_STH + 3*B_STH)*2)
#define SMEM_STREAM_MAX 61440

// ---------------- scratch (device globals; no runtime allocation) -------------
__device__ __align__(16) __half g_hcat[(size_t)TN*DD];
__device__ __align__(16) __half g_h   [(size_t)TN*DD];
__device__ __align__(16) __half g_hT  [(size_t)TN*DD];   // [T][D][N]
__device__ __align__(16) __half g_graph[(size_t)TT*NPTS*NPTS];
__device__ __align__(16) __half g_z1  [(size_t)TN*DD];
__device__ __align__(16) __half g_qkv [(size_t)TN*D3];
__device__ __align__(16) __half g_qkv2[(size_t)TN*D3];
__device__ float g_kvs_s [(size_t)TT*HH*HD*HD];
__device__ float g_ksum_s[(size_t)TT*HH*HD];
__device__ float g_kvs_t [(size_t)NPTS*HH*HD*HD];
__device__ float g_ksum_t[(size_t)NPTS*HH*HD];
__device__ float g_kvs_s2 [(size_t)TT*HH*HD*HD];
__device__ float g_ksum_s2[(size_t)TT*HH*HD];
__device__ float g_kvs_t2 [(size_t)NPTS*HH*HD*HD];
__device__ float g_ksum_t2[(size_t)NPTS*HH*HD];
__device__ __align__(16) __half g_cat2 [(size_t)TN*D2];
__device__ __align__(16) __half g_cat2b[(size_t)TN*D2];
__device__ __align__(16) __half g_att0[(size_t)TN*DD];
__device__ float  g_att1[(size_t)TN*DD];
__device__ float  g_p0  [(size_t)TN*DD];
__device__ float  g_p1  [(size_t)TN*DD];
__device__ __align__(16) __half g_h1  [(size_t)TN*DD];
__device__ float  g_t2  [(size_t)TN*DD];
__device__ __align__(16) __half g_h2t [(size_t)NPTS*TD];
__device__ float  g_part[(size_t)SPLITK*NPTS*DD];
__device__ __align__(16) __half g_y   [(size_t)NPTS*DD];
__device__ __align__(16) __half g_yh  [(size_t)NPTS*D2];
__device__ __align__(16) __half g_wtsh[(size_t)16000000];

// offsets into g_wtsh (halves)
#define O_ADP   0L
#define O_WTP   11680000L
#define O_QKVW  11690816L
#define O_OPW   11755712L
#define O_PWW   11798976L
#define O_FC1   11820608L
#define O_FC2   11842240L
#define O_EPW   11863872L
#define O_ENC1  15811712L
#define O_ENC2  15876608L
#define O_OUTW  15941504L

// ---------------- cp.async issue helpers ----------------------------------------
__device__ __forceinline__ void issue_a(const __half* __restrict__ A, unsigned sAs,
                                        int bm, int k0, int kend, int M, long K, int tid)
{
    #pragma unroll
    for (int p = 0; p < 2; p++) {
        int idx = tid + p * 256;
        int m = idx >> 2, kq = (idx & 3) << 3;
        int gm = bm + m;
        int rem = kend - (k0 + kq);
        int sz = (gm < M && rem >= 8) ? 16 : 0;
        const __half* src = sz ? A + (long)gm * K + k0 + kq : A;
        unsigned dst = sAs + (unsigned)(m * SMA + kq) * 2u;
        asm volatile("cp.async.ca.shared.global [%0],[%1],16,%2;"
                     :: "r"(dst), "l"(src), "r"(sz));
    }
}

__device__ __forceinline__ void issue_b(const __half* __restrict__ B, unsigned sBs,
                                        int bn, int k0, int kend, int Nc, long K, int tid)
{
    int n = tid >> 2, kq = (tid & 3) << 3;
    int gn = bn + n;
    int rem = kend - (k0 + kq);
    int sz = (gn < Nc && rem >= 8) ? 16 : 0;
    const __half* src = sz ? B + (long)gn * K + k0 + kq : B;
    unsigned dst = sBs + (unsigned)(n * SMA + kq) * 2u;
    asm volatile("cp.async.ca.shared.global [%0],[%1],16,%2;"
                 :: "r"(dst), "l"(src), "r"(sz));
}

// ---------------- fp16 MMA on a k32 chunk ---------------------------------------
__device__ __forceinline__ void mma_chunk(const __half* __restrict__ As, int sbA,
                                          const __half* __restrict__ Bs, int sbB,
                                          int wm, int wn, int lane, float (*acc)[4][4])
{
    int r = lane >> 2, c2 = (lane & 3) << 1;
    #pragma unroll
    for (int ks = 0; ks < 2; ks++) {
        int k0 = ks * 16;
        unsigned a[2][4], b[4][2];
        #pragma unroll
        for (int mt = 0; mt < 2; mt++) {
            const __half* p = As + (wm * 32 + mt * 16 + r) * sbA + k0 + c2;
            a[mt][0] = *reinterpret_cast<const unsigned*>(p);
            a[mt][1] = *reinterpret_cast<const unsigned*>(p + 8 * sbA);
            a[mt][2] = *reinterpret_cast<const unsigned*>(p + 8);
            a[mt][3] = *reinterpret_cast<const unsigned*>(p + 8 * sbA + 8);
        }
        #pragma unroll
        for (int nt = 0; nt < 4; nt++) {
            const __half* q = Bs + (wn * 32 + nt * 8 + r) * sbB + k0 + c2;
            b[nt][0] = *reinterpret_cast<const unsigned*>(q);
            b[nt][1] = *reinterpret_cast<const unsigned*>(q + 8);
        }
        #pragma unroll
        for (int mt = 0; mt < 2; mt++)
            #pragma unroll
            for (int nt = 0; nt < 4; nt++)
                asm("mma.sync.aligned.m16n8k16.row.col.f32.f16.f16.f32 "
                    "{%0,%1,%2,%3},{%4,%5,%6,%7},{%8,%9},{%0,%1,%2,%3};"
                    : "+f"(acc[mt][nt][0]), "+f"(acc[mt][nt][1]),
                      "+f"(acc[mt][nt][2]), "+f"(acc[mt][nt][3])
                    : "r"(a[mt][0]), "r"(a[mt][1]), "r"(a[mt][2]), "r"(a[mt][3]),
                      "r"(b[nt][0]), "r"(b[nt][1]));
    }
}

// ---------------- epilogue -------------------------------------------------------
template<bool RELU, bool ACC, bool SPLIT, typename TC>
__device__ __forceinline__ void epilogue(float (*acc)[4][4], const float* bias,
                                         TC* __restrict__ C, int bm, int bn,
                                         int M, int Nc, int wm, int wn, int lane)
{
    int r = lane >> 2, c2 = (lane & 3) << 1;
    #pragma unroll
    for (int mt = 0; mt < 2; mt++) {
        #pragma unroll
        for (int nt = 0; nt < 4; nt++) {
            int gm0 = bm + wm * 32 + mt * 16 + r;
            int gn0 = bn + wn * 32 + nt * 8 + c2;
            #pragma unroll
            for (int hh = 0; hh < 2; hh++) {
                int gm = gm0 + hh * 8;
                if (gm >= M) continue;
                #pragma unroll
                for (int j = 0; j < 2; j++) {
                    int gn = gn0 + j;
                    if (gn >= Nc) continue;
                    float v = acc[mt][nt][hh * 2 + j];
                    if (!SPLIT && bias) v += bias[gn];
                    if (RELU) v = fmaxf(v, 0.f);
                    long ci = (long)gm * Nc + gn;
                    if (ACC) v += (float)C[ci];
                    C[ci] = (TC)v;
                }
            }
        }
    }
}

// ---------------- batched / split fp16 GEMM (B always [n][k]) -------------------
template<bool SPLIT, typename TC>
__global__ void __launch_bounds__(256)
gemm_kernel(const __half* __restrict__ A, const __half* __restrict__ B,
            const float* __restrict__ bias, TC* __restrict__ C,
            int M, int K, int Nc, long sA, long sB_, long sC)
{
    extern __shared__ __half dsmh[];
    int tid = threadIdx.x;
    int bm = blockIdx.y * 128, bn = blockIdx.x * 64;
    int kbeg = 0, kend = K;
    if (SPLIT) {
        int z = blockIdx.z;
        kbeg = z * KCHUNK;
        kend = min(K, kbeg + KCHUNK);
        C += (long)z * M * Nc;
    } else {
        int z = blockIdx.z;
        A += z * sA; B += z * sB_; C += z * sC;
    }
    int w = tid >> 5, lane = tid & 31;
    int wm = w >> 1, wn = w & 1;
    float acc[2][4][4];
    #pragma unroll
    for (int mt = 0; mt < 2; mt++)
        #pragma unroll
        for (int nt = 0; nt < 4; nt++)
            #pragma unroll
            for (int q = 0; q < 4; q++) acc[mt][nt][q] = 0.f;

    unsigned sbase = (unsigned)__cvta_generic_to_shared(dsmh);
    unsigned sA0 = sbase;
    unsigned sB0 = sbase + 3u * A_STH * 2u;

    int nk = (kend - kbeg + 31) >> 5;
    issue_a(A, sA0, bm, kbeg, kend, M, K, tid);
    issue_b(B, sB0, bn, kbeg, kend, Nc, K, tid);
    asm volatile("cp.async.commit_group;" ::: "memory");
    issue_a(A, sA0 + A_STH * 2u, bm, kbeg + 32, kend, M, K, tid);
    issue_b(B, sB0 + B_STH * 2u, bn, kbeg + 32, kend, Nc, K, tid);
    asm volatile("cp.async.commit_group;" ::: "memory");

    for (int it = 0; it < nk; it++) {
        asm volatile("cp.async.wait_group 1;" ::: "memory");
        __syncthreads();
        int s2 = (it + 2) % 3;
        int kn = kbeg + (it + 2) * 32;
        issue_a(A, sA0 + (unsigned)s2 * A_STH * 2u, bm, kn, kend, M, K, tid);
        issue_b(B, sB0 + (unsigned)s2 * B_STH * 2u, bn, kn, kend, Nc, K, tid);
        asm volatile("cp.async.commit_group;" ::: "memory");
        int sc = it % 3;
        mma_chunk(dsmh + sc * A_STH, SMA, dsmh + 3 * A_STH + sc * B_STH, SMA,
                  wm, wn, lane, acc);
    }
    epilogue<false, false, SPLIT, TC>(acc, bias, C, bm, bn, M, Nc, wm, wn, lane);
}

// ---------------- persistent-B streaming GEMM (NN, non-batched) -----------------
template<bool RELU, bool ACC, typename TC>
__global__ void __launch_bounds__(256)
gemm_stream(const __half* __restrict__ A, const __half* __restrict__ Bt,
            const float* __restrict__ bias, TC* __restrict__ C,
            int M, int K, int Nc, int KP)
{
    extern __shared__ __half dsmh[];
    __half* Asm = dsmh;
    __half* Bsm = dsmh + 3 * A_STH;
    int tid = threadIdx.x;
    int bn = blockIdx.x * 64;
    int nkc = (K + 31) >> 5;
    int KP32 = nkc * 32;
    int MT = (M + 127) >> 7;
    int w = tid >> 5, lane = tid & 31;
    int wm = w >> 1, wn = w & 1;

    unsigned sbase = (unsigned)__cvta_generic_to_shared(dsmh);
    unsigned sA0 = sbase;
    unsigned sB0 = sbase + 3u * A_STH * 2u;

    int nchunk = KP32 >> 3;
    for (int e = tid; e < 64 * nchunk; e += 256) {
        int n = e / nchunk, kc8 = e - n * nchunk;
        int k = kc8 << 3;
        int gn = bn + n;
        int sz = (gn < Nc && k < K) ? 16 : 0;
        const __half* src = sz ? Bt + (long)gn * K + k : Bt;
        unsigned dst = sB0 + (unsigned)(n * KP + k) * 2u;
        asm volatile("cp.async.ca.shared.global [%0],[%1],16,%2;"
                     :: "r"(dst), "l"(src), "r"(sz));
    }

    int mt_i = blockIdx.y;
    int kc_i = 0;
    if (mt_i < MT) issue_a(A, sA0, mt_i * 128, 0, K, M, K, tid);
    asm volatile("cp.async.commit_group;" ::: "memory");
    if (++kc_i == nkc) { kc_i = 0; mt_i += gridDim.y; }
    if (mt_i < MT) issue_a(A, sA0 + A_STH * 2u, mt_i * 128, kc_i * 32, K, M, K, tid);
    asm volatile("cp.async.commit_group;" ::: "memory");
    if (++kc_i == nkc) { kc_i = 0; mt_i += gridDim.y; }

    float acc[2][4][4];
    int stage = 0;
    for (int mt = blockIdx.y; mt < MT; mt += gridDim.y) {
        #pragma unroll
        for (int mtt = 0; mtt < 2; mtt++)
            #pragma unroll
            for (int nt = 0; nt < 4; nt++)
                #pragma unroll
                for (int q = 0; q < 4; q++) acc[mtt][nt][q] = 0.f;
        for (int kc = 0; kc < nkc; kc++) {
            asm volatile("cp.async.wait_group 1;" ::: "memory");
            __syncthreads();
            int s2 = (stage + 2) % 3;
            if (mt_i < MT) issue_a(A, sA0 + (unsigned)s2 * A_STH * 2u,
                                   mt_i * 128, kc_i * 32, K, M, K, tid);
            asm volatile("cp.async.commit_group;" ::: "memory");
            if (++kc_i == nkc) { kc_i = 0; mt_i += gridDim.y; }
            mma_chunk(Asm + stage * A_STH, SMA, Bsm + kc * 32, KP, wm, wn, lane, acc);
            stage = (stage + 1) % 3;
        }
        epilogue<RELU, ACC, false, TC>(acc, bias, C, mt * 128, bn, M, Nc, wm, wn, lane);
    }
}

// ---------------- fused relu-softmax normalize (fp16 in/out) --------------------
__global__ void normgraph_kernel(__half* __restrict__ g)
{
    long row = (long)blockIdx.x * 8 + (threadIdx.x >> 5);
    if (row >= (long)TN) return;
    int lane = threadIdx.x & 31;
    uint4* p = reinterpret_cast<uint4*>(g + row * NPTS);
    float v[2][8]; uint4 u;
    float m = 0.f;
    #pragma unroll
    for (int rch = 0; rch < 2; rch++) {
        int c = lane + rch * 32;
        if (c < 50) {
            u = p[c];
            const __half2* hp = reinterpret_cast<const __half2*>(&u);
            #pragma unroll
            for (int j = 0; j < 4; j++) {
                float2 f = __half22float2(hp[j]);
                v[rch][2 * j] = f.x; v[rch][2 * j + 1] = f.y;
                m = fmaxf(m, fmaxf(f.x, f.y));
            }
        }
    }
    #pragma unroll
    for (int o = 16; o > 0; o >>= 1) m = fmaxf(m, __shfl_xor_sync(~0u, m, o));
    float s = 0.f;
    #pragma unroll
    for (int rch = 0; rch < 2; rch++) {
        int c = lane + rch * 32;
        if (c < 50) {
            #pragma unroll
            for (int j = 0; j < 8; j++) {
                float e = __expf(fmaxf(v[rch][j], 0.f) - m);
                v[rch][j] = e; s += e;
            }
        }
    }
    #pragma unroll
    for (int o = 16; o > 0; o >>= 1) s += __shfl_xor_sync(~0u, s, o);
    float inv = 1.f / s;
    #pragma unroll
    for (int rch = 0; rch < 2; rch++) {
        int c = lane + rch * 32;
        if (c < 50) {
            uint4 ou;
            __half2* hp = reinterpret_cast<__half2*>(&ou);
            #pragma unroll
            for (int j = 0; j < 4; j++)
                hp[j] = __floats2half2_rn(v[rch][2 * j] * inv, v[rch][2 * j + 1] * inv);
            p[c] = ou;
        }
    }
}

// ---------------- weight conversion kernels -------------------------------------
__global__ void rnd2h_kernel(const float* __restrict__ src, __half* __restrict__ dst, long n2)
{
    long i = (long)blockIdx.x * 256 + threadIdx.x;
    if (i >= n2) return;
    float2 f = reinterpret_cast<const float2*>(src)[i];
    reinterpret_cast<__half2*>(dst)[i] = __floats2half2_rn(f.x, f.y);
}

__global__ void trnd_kernel(const float* __restrict__ src, __half* __restrict__ dst,
                            int K, int Nc)
{
    long j = (long)blockIdx.x * 256 + threadIdx.x;
    if (j >= (long)K * Nc) return;
    int n = (int)(j / K); long k = j - (long)n * K;
    dst[j] = __float2half_rn(src[k * Nc + n]);
}

__global__ void trnd_tiled_kernel(const float* __restrict__ src, __half* __restrict__ dst,
                                  int K, int Nc)
{
    __shared__ float tile[32][33];
    int k0 = blockIdx.x * 32, n0 = blockIdx.y * 32;
    int tx = threadIdx.x & 31, ty = threadIdx.x >> 5;
    #pragma unroll
    for (int i = ty; i < 32; i += 8) {
        int k = k0 + i, n = n0 + tx;
        tile[i][tx] = (k < K && n < Nc) ? src[(long)k * Nc + n] : 0.f;
    }
    __syncthreads();
    #pragma unroll
    for (int i = ty; i < 32; i += 8) {
        int n = n0 + i, k = k0 + tx;
        if (n < Nc && k < K) dst[(long)n * K + k] = __float2half_rn(tile[tx][i]);
    }
}

// ---------------- input proj + concat adaptive embedding ------------------------
__global__ void hcat_kernel(const float* __restrict__ x, const float* __restrict__ W_in,
                            const float* __restrict__ b_in, const __half* __restrict__ adp_h,
                            __half* __restrict__ hcat)
{
    long idx = (long)blockIdx.x * 256 + threadIdx.x;
    if (idx >= (long)TN * DD) return;
    long tn = idx / DD; int j = (int)(idx - tn * DD);
    int t = (int)(tn / NPTS), n = (int)(tn - (long)t * NPTS);
    __half v;
    if (j < 24) {
        const float* xr = x + ((long)n * TT + t) * 3;
        v = __float2half_rn(b_in[j] + xr[0] * W_in[0 * 24 + j]
                            + xr[1] * W_in[1 * 24 + j] + xr[2] * W_in[2 * 24 + j]);
    } else {
        v = adp_h[tn * 80 + (j - 24)];
    }
    hcat[idx] = v;
}

// ---------------- h -> hT [T][D][N] ----------------------------------------------
__global__ void transpose_hT_kernel(const __half* __restrict__ h, __half* __restrict__ hT)
{
    long idx = (long)blockIdx.x * 256 + threadIdx.x;
    if (idx >= (long)TN * DD) return;
    long t = idx / ((long)NPTS * DD);
    long r = idx - t * ((long)NPTS * DD);
    long n = r / DD;
    long d = r - n * DD;
    hT[t * (long)DD * NPTS + d * NPTS + n] = h[idx];
}

// ---------------- linear attention: kvs + ksum ----------------------------------
__global__ void kvs_kernel(const __half* __restrict__ qkv, long sB, long sL, int L,
                           float* __restrict__ kvs, float* __restrict__ ksum)
{
    int b = blockIdx.x, h = blockIdx.y;
    int w = threadIdx.x >> 5, lane = threadIdx.x & 31;
    int chunk = (L + 7) >> 3;
    int l0 = w * chunk, l1 = min(L, l0 + chunk);
    const __half* base = qkv + (long)b * sB + h * HD;
    float acc[HD];
    #pragma unroll
    for (int m = 0; m < HD; m++) acc[m] = 0.f;
    float accs = 0.f;
    for (int l = l0; l < l1; l++) {
        const __half* row = base + (long)l * sL;
        float kk = (lane < HD) ? __half2float(row[DD + lane]) : 0.f;
        float vv = (lane < HD) ? __half2float(row[2 * DD + lane]) : 0.f;
        float ss = kk * kk;
        #pragma unroll
        for (int o = 16; o > 0; o >>= 1) ss += __shfl_xor_sync(~0u, ss, o);
        float inv = 1.f / fmaxf(sqrtf(ss), 1e-12f);
        float kin = kk * inv;
        accs += kin;
        #pragma unroll
        for (int m = 0; m < HD; m++) {
            float km = __shfl_sync(~0u, kin, m);
            acc[m] += km * vv;
        }
    }
    __shared__ float red[8][HD][HD + 2];
    __shared__ float redk[8][32];
    if (lane < HD) {
        #pragma unroll
        for (int m = 0; m < HD; m++) red[w][m][lane] = acc[m];
    }
    redk[w][lane] = accs;
    __syncthreads();
    long basec = ((long)b * HH + h);
    for (int cell = threadIdx.x; cell < HD * HD; cell += 256) {
        int m = cell / HD, d = cell - m * HD;
        float s = 0.f;
        #pragma unroll
        for (int ww = 0; ww < 8; ww++) s += red[ww][m][d];
        kvs[basec * (HD * HD) + cell] = s;
    }
    if (threadIdx.x < HD) {
        float s = 0.f;
        #pragma unroll
        for (int ww = 0; ww < 8; ww++) s += redk[ww][threadIdx.x];
        ksum[basec * HD + threadIdx.x] = s;
    }
}

// ---------------- fused spatial+temporal attention output -----------------------
__global__ void attnout2_kernel(const __half* __restrict__ qkv,
                                const float* __restrict__ kvs_s, const float* __restrict__ ksum_s,
                                const float* __restrict__ kvs_t, const float* __restrict__ ksum_t,
                                __half* __restrict__ cat2)
{
    int n = blockIdx.x, t = blockIdx.y;
    int tid = threadIdx.x;
    long tok = (long)t * NPTS + n;
    const __half* row = qkv + tok * D3;
    __shared__ float sq[DD], sv[DD], sinv[HH], sden_s[HH], sden_t[HH];
    if (tid < DD) {
        sq[tid] = __half2float(row[tid]);
        sv[tid] = __half2float(row[2 * DD + tid]);
    }
    __syncthreads();
    if (tid < HH) {
        const float* qh = sq + tid * HD;
        float ss = 0.f;
        #pragma unroll
        for (int m = 0; m < HD; m++) ss += qh[m] * qh[m];
        float inv = 1.f / fmaxf(sqrtf(ss), 1e-12f);
        sinv[tid] = inv;
        const float* ks = ksum_s + ((long)t * HH + tid) * HD;
        const float* kt = ksum_t + ((long)n * HH + tid) * HD;
        float ds = 0.f, dt = 0.f;
        #pragma unroll
        for (int m = 0; m < HD; m++) { ds += qh[m] * ks[m]; dt += qh[m] * kt[m]; }
        sden_s[tid] = ds * inv + (float)NPTS;
        sden_t[tid] = dt * inv + (float)TT;
    }
    __syncthreads();
    if (tid < DD) {
        int h = tid / HD, d = tid - h * HD;
        const float* qh = sq + h * HD;
        const float* kv_s = kvs_s + ((long)t * HH + h) * (HD * HD) + d;
        const float* kv_t = kvs_t + ((long)n * HH + h) * (HD * HD) + d;
        float ss = 0.f, st = 0.f;
        #pragma unroll
        for (int m = 0; m < HD; m++) {
            ss += qh[m] * kv_s[m * HD];
            st += qh[m] * kv_t[m * HD];
        }
        float inv = sinv[h], vv = sv[tid];
        cat2[tok * D2 + tid]      = __float2half_rn((ss * inv + (float)NPTS * vv) / sden_s[h]);
        cat2[tok * D2 + DD + tid] = __float2half_rn((st * inv + (float)TT   * vv) / sden_t[h]);
    }
}

// ---------------- fused combine + LayerNorm --------------------------------------
__global__ void combine_ln_kernel(const __half* __restrict__ h, const __half* __restrict__ a0,
                                  const float* __restrict__ a1, const float* __restrict__ p0,
                                  const float* __restrict__ p1, const float* __restrict__ gam,
                                  const float* __restrict__ bet, __half* __restrict__ out)
{
    long row = blockIdx.x; int tid = threadIdx.x;
    __shared__ float red[4];
    long i = row * DD + tid;
    float v = 0.f;
    if (tid < DD)
        v = 2.f * (__half2float(h[i]) + __half2float(a0[i]) * p0[i] + 0.01f * a1[i] * p1[i]);
    float s = (tid < DD) ? v : 0.f;
    #pragma unroll
    for (int o = 16; o > 0; o >>= 1) s += __shfl_xor_sync(~0u, s, o);
    if ((tid & 31) == 0) red[tid >> 5] = s;
    __syncthreads();
    float mean = (red[0] + red[1] + red[2] + red[3]) / (float)DD;
    __syncthreads();
    float d = (tid < DD) ? (v - mean) : 0.f;
    float s2 = d * d;
    #pragma unroll
    for (int o = 16; o > 0; o >>= 1) s2 += __shfl_xor_sync(~0u, s2, o);
    if ((tid & 31) == 0) red[tid >> 5] = s2;
    __syncthreads();
    float var = (red[0] + red[1] + red[2] + red[3]) / (float)DD;
    if (tid < DD) out[i] = __float2half_rn(d * rsqrtf(var + 1e-5f) * gam[tid] + bet[tid]);
}

// ln + residual, writing DIRECTLY into transposed layout h2t[n][t*DD+d]
__global__ void ln_res_t_kernel(const __half* __restrict__ a, const float* __restrict__ b,
                                const float* __restrict__ gam, const float* __restrict__ bet,
                                __half* __restrict__ h2t)
{
    long row = blockIdx.x; int tid = threadIdx.x;
    __shared__ float red[4];
    long i = row * DD + tid;
    float v = 0.f;
    if (tid < DD) v = __half2float(a[i]) + b[i];
    float s = (tid < DD) ? v : 0.f;
    #pragma unroll
    for (int o = 16; o > 0; o >>= 1) s += __shfl_xor_sync(~0u, s, o);
    if ((tid & 31) == 0) red[tid >> 5] = s;
    __syncthreads();
    float mean = (red[0] + red[1] + red[2] + red[3]) / (float)DD;
    __syncthreads();
    float d = (tid < DD) ? (v - mean) : 0.f;
    float s2 = d * d;
    #pragma unroll
    for (int o = 16; o > 0; o >>= 1) s2 += __shfl_xor_sync(~0u, s2, o);
    if ((tid & 31) == 0) red[tid >> 5] = s2;
    __syncthreads();
    float var = (red[0] + red[1] + red[2] + red[3]) / (float)DD;
    if (tid < DD) {
        long t = row / NPTS, n = row - t * NPTS;
        h2t[n * (long)TD + t * DD + tid] =
            __float2half_rn(d * rsqrtf(var + 1e-5f) * gam[tid] + bet[tid]);
    }
}

// ---------------- split-K deterministic reduction -------------------------------
__global__ void splitk_reduce_kernel(const float* __restrict__ part, const float* __restrict__ bias,
                                     __half* __restrict__ y, int MN, int Z, int Nc)
{
    int i = blockIdx.x * 256 + threadIdx.x;
    if (i >= MN) return;
    float s = bias[i % Nc];
    for (int z = 0; z < Z; z++) s += part[(long)z * MN + i];
    y[i] = __float2half_rn(s);
}

// ---------------- streaming GEMM launcher ---------------------------------------
template<bool RELU, bool ACC, typename TC>
static void launch_stream_t(const __half* A, const __half* Bt, const float* bias, TC* C,
                            int M, int K, int Nc, cudaStream_t st)
{
    int nkc = (K + 31) / 32;
    int KP = nkc * 32 + 8;
    int smem = 3 * A_STH * 2 + 64 * KP * 2;
    int nx = (Nc + 63) / 64;
    int MT = (M + 127) / 128;
    int gy = (444 + nx - 1) / nx;
    if (gy > MT) gy = MT;
    gemm_stream<RELU, ACC, TC><<<dim3(nx, gy), 256, smem, st>>>(A, Bt, bias, C, M, K, Nc, KP);
}

// ---------------- host orchestration --------------------------------------------
static void run_attention(const __half* x4, const __half* qwT, const __half* owT,
                          const float* ob, __half* qkv,
                          float* kvs_s, float* ksum_s, float* kvs_t, float* ksum_t,
                          __half* cat2, __half* att_h, float* att_f, cudaStream_t st)
{
    launch_stream_t<false, false, __half>(x4, qwT, nullptr, qkv, TN, DD, D3, st);
    kvs_kernel<<<dim3(TT, HH), 256, 0, st>>>(qkv, (long)NPTS * D3, (long)D3, NPTS, kvs_s, ksum_s);
    kvs_kernel<<<dim3(NPTS, HH), 256, 0, st>>>(qkv, (long)D3, (long)NPTS * D3, TT, kvs_t, ksum_t);
    attnout2_kernel<<<dim3(NPTS, TT), 128, 0, st>>>(qkv, kvs_s, ksum_s, kvs_t, ksum_t, cat2);
    if (att_h) launch_stream_t<false, false, __half>(cat2, owT, ob, att_h, TN, D2, DD, st);
    else       launch_stream_t<false, false, float >(cat2, owT, ob, att_f, TN, D2, DD, st);
}

extern "C" void kernel_launch(void* const* d_in, const int* in_sizes, int n_in,
                              void* d_out, int out_size)
{
    (void)in_sizes; (void)n_in; (void)out_size;
    const float* x     = (const float*)d_in[0];
    const float* W_in  = (const float*)d_in[1];
    const float* b_in  = (const float*)d_in[2];
    const float* adp   = (const float*)d_in[3];
    const float* W_tp  = (const float*)d_in[4];
    const float* b_tp  = (const float*)d_in[5];
    const float* qkv_w = (const float*)d_in[6];
    const float* op_w  = (const float*)d_in[7];
    const float* op_b  = (const float*)d_in[8];
    const float* pw_w  = (const float*)d_in[9];
    const float* pw_b  = (const float*)d_in[10];
    const float* fc_w1 = (const float*)d_in[11];
    const float* fc_b1 = (const float*)d_in[12];
    const float* fc_w2 = (const float*)d_in[13];
    const float* fc_b2 = (const float*)d_in[14];
    const float* ln1_g = (const float*)d_in[15];
    const float* ln1_b = (const float*)d_in[16];
    const float* ln2_g = (const float*)d_in[17];
    const float* ln2_b = (const float*)d_in[18];
    const float* ep_w  = (const float*)d_in[19];
    const float* ep_b  = (const float*)d_in[20];
    const float* enc_w1= (const float*)d_in[21];
    const float* enc_b1= (const float*)d_in[22];
    const float* enc_w2= (const float*)d_in[23];
    const float* enc_b2= (const float*)d_in[24];
    const float* out_w = (const float*)d_in[25];
    const float* out_b = (const float*)d_in[26];
    float* out = (float*)d_out;

    static cudaStream_t s1 = nullptr, s2 = nullptr;
    static cudaEvent_t evF, evAdp, evHT, evB1, evW;
    if (!s1) {
        cudaStreamCreateWithFlags(&s1, cudaStreamNonBlocking);
        cudaStreamCreateWithFlags(&s2, cudaStreamNonBlocking);
        cudaEventCreateWithFlags(&evF,   cudaEventDisableTiming);
        cudaEventCreateWithFlags(&evAdp, cudaEventDisableTiming);
        cudaEventCreateWithFlags(&evHT,  cudaEventDisableTiming);
        cudaEventCreateWithFlags(&evB1,  cudaEventDisableTiming);
        cudaEventCreateWithFlags(&evW,   cudaEventDisableTiming);
        cudaFuncSetAttribute(gemm_kernel<false, __half>,
                             cudaFuncAttributeMaxDynamicSharedMemorySize, SMEM_BATCH);
        cudaFuncSetAttribute(gemm_kernel<true, float>,
                             cudaFuncAttributeMaxDynamicSharedMemorySize, SMEM_BATCH);
        cudaFuncSetAttribute(gemm_stream<false, false, __half>,
                             cudaFuncAttributeMaxDynamicSharedMemorySize, SMEM_STREAM_MAX);
        cudaFuncSetAttribute(gemm_stream<true, false, __half>,
                             cudaFuncAttributeMaxDynamicSharedMemorySize, SMEM_STREAM_MAX);
        cudaFuncSetAttribute(gemm_stream<false, true, __half>,
                             cudaFuncAttributeMaxDynamicSharedMemorySize, SMEM_STREAM_MAX);
        cudaFuncSetAttribute(gemm_stream<false, false, float>,
                             cudaFuncAttributeMaxDynamicSharedMemorySize, SMEM_STREAM_MAX);
    }

    __half *hcat, *h, *hT, *graph, *z1, *qkv, *qkv2, *cat2, *cat2b, *att0;
    __half *h1, *h2t, *y, *yh, *wtsh;
    float *kvs_s, *ksum_s, *kvs_t, *ksum_t, *kvs_s2, *ksum_s2, *kvs_t2, *ksum_t2;
    float *att1, *p0, *p1, *t2, *part;
    cudaGetSymbolAddress((void**)&hcat, g_hcat);
    cudaGetSymbolAddress((void**)&h,    g_h);
    cudaGetSymbolAddress((void**)&hT,   g_hT);
    cudaGetSymbolAddress((void**)&graph,g_graph);
    cudaGetSymbolAddress((void**)&z1,   g_z1);
    cudaGetSymbolAddress((void**)&qkv,  g_qkv);
    cudaGetSymbolAddress((void**)&qkv2, g_qkv2);
    cudaGetSymbolAddress((void**)&kvs_s,  g_kvs_s);
    cudaGetSymbolAddress((void**)&ksum_s, g_ksum_s);
    cudaGetSymbolAddress((void**)&kvs_t,  g_kvs_t);
    cudaGetSymbolAddress((void**)&ksum_t, g_ksum_t);
    cudaGetSymbolAddress((void**)&kvs_s2, g_kvs_s2);
    cudaGetSymbolAddress((void**)&ksum_s2,g_ksum_s2);
    cudaGetSymbolAddress((void**)&kvs_t2, g_kvs_t2);
    cudaGetSymbolAddress((void**)&ksum_t2,g_ksum_t2);
    cudaGetSymbolAddress((void**)&cat2,  g_cat2);
    cudaGetSymbolAddress((void**)&cat2b, g_cat2b);
    cudaGetSymbolAddress((void**)&att0, g_att0);
    cudaGetSymbolAddress((void**)&att1, g_att1);
    cudaGetSymbolAddress((void**)&p0,   g_p0);
    cudaGetSymbolAddress((void**)&p1,   g_p1);
    cudaGetSymbolAddress((void**)&h1,   g_h1);
    cudaGetSymbolAddress((void**)&t2,   g_t2);
    cudaGetSymbolAddress((void**)&h2t,  g_h2t);
    cudaGetSymbolAddress((void**)&part, g_part);
    cudaGetSymbolAddress((void**)&y,    g_y);
    cudaGetSymbolAddress((void**)&yh,   g_yh);
    cudaGetSymbolAddress((void**)&wtsh, g_wtsh);

    __half* adp_h  = wtsh + O_ADP;
    __half* WtpT   = wtsh + O_WTP;
    __half* qkvwT  = wtsh + O_QKVW;
    __half* opwT   = wtsh + O_OPW;
    __half* pwwT   = wtsh + O_PWW;
    __half* fc1T   = wtsh + O_FC1;
    __half* fc2T   = wtsh + O_FC2;
    __half* epwT   = wtsh + O_EPW;
    __half* enc1T  = wtsh + O_ENC1;
    __half* enc2T  = wtsh + O_ENC2;
    __half* outwT  = wtsh + O_OUTW;

    // ======== FORK s2: all weight conversions off the critical path ========
    cudaEventRecord(evF, 0);
    cudaStreamWaitEvent(s2, evF, 0);
    #define TRND(src, dst, K_, N_) \
        trnd_kernel<<<(((long)(K_) * (N_)) + 255) / 256, 256, 0, s2>>>(src, dst, K_, N_)
    TRND(W_tp, WtpT, DD, DD);
    TRND(qkv_w,            qkvwT,             DD, D3);
    TRND(qkv_w + DD * D3,  qkvwT + D3 * DD,   DD, D3);
    TRND(op_w,             opwT,              D2, DD);
    TRND(op_w + D2 * DD,   opwT + DD * D2,    D2, DD);
    TRND(pw_w,             pwwT,              DD, DD);
    TRND(pw_w + DD * DD,   pwwT + DD * DD,    DD, DD);
    TRND(fc_w1, fc1T, DD, D2);
    TRND(fc_w2, fc2T, D2, DD);
    for (int i = 0; i < 3; i++) {
        TRND(enc_w1 + (long)i * DD * D2, enc1T + (long)i * D2 * DD, DD, D2);
        TRND(enc_w2 + (long)i * D2 * DD, enc2T + (long)i * DD * D2, D2, DD);
    }
    TRND(out_w, outwT, DD, TT);
    trnd_tiled_kernel<<<dim3((TD + 31) / 32, (DD + 31) / 32), 256, 0, s2>>>(ep_w, epwT, TD, DD);
    cudaEventRecord(evW, s2);

    // ---- main: adp conversion (graph branch + hcat need it) ----
    {
        long n2 = (long)TT * NPTS * 80 / 2;
        rnd2h_kernel<<<(n2 + 255) / 256, 256>>>(adp, adp_h, n2);
    }

    // ======== FORK s1: graph branch ========
    cudaEventRecord(evAdp, 0);
    cudaStreamWaitEvent(s1, evAdp, 0);
    gemm_kernel<false, __half><<<dim3(7, 4, TT), 256, SMEM_BATCH, s1>>>(
        adp_h, adp_h, nullptr, graph, NPTS, 80, NPTS,
        (long)NPTS * 80, (long)NPTS * 80, (long)NPTS * NPTS);
    normgraph_kernel<<<(TN + 7) / 8, 256, 0, s1>>>(graph);

    // ---- main: h chain (joins weight stream before first weight consumer) ----
    hcat_kernel<<<((long)TN * DD + 255) / 256, 256>>>(x, W_in, b_in, adp_h, hcat);
    cudaStreamWaitEvent(0, evW, 0);
    launch_stream_t<false, false, __half>(hcat, WtpT, b_tp, h, TN, DD, DD, 0);
    transpose_hT_kernel<<<((long)TN * DD + 255) / 256, 256>>>(h, hT);
    cudaEventRecord(evHT, 0);

    // ======== s1: z1 + attention branch 1 (weights ready transitively) ========
    cudaStreamWaitEvent(s1, evHT, 0);
    gemm_kernel<false, __half><<<dim3(2, 4, TT), 256, SMEM_BATCH, s1>>>(
        graph, hT, nullptr, z1, NPTS, NPTS, DD,
        (long)NPTS * NPTS, (long)DD * NPTS, (long)NPTS * DD);
    run_attention(z1, qkvwT + D3 * DD, opwT + DD * D2, op_b + DD, qkv2,
                  kvs_s2, ksum_s2, kvs_t2, ksum_t2, cat2b, nullptr, att1, s1);
    cudaEventRecord(evB1, s1);

    // ---- main (concurrent): p0, attention branch 0, p1 ----
    launch_stream_t<false, false, float>(h, pwwT, pw_b, p0, TN, DD, DD, 0);
    run_attention(h, qkvwT, opwT, op_b, qkv, kvs_s, ksum_s, kvs_t, ksum_t,
                  cat2, att0, nullptr, 0);
    launch_stream_t<false, false, float>(att0, pwwT + DD * DD, pw_b + DD, p1, TN, DD, DD, 0);

    // ======== JOIN ========
    cudaStreamWaitEvent(0, evB1, 0);

    combine_ln_kernel<<<TN, 128>>>(h, att0, att1, p0, p1, ln1_g, ln1_b, h1);
    launch_stream_t<true,  false, __half>(h1,   fc1T, fc_b1, cat2, TN, DD, D2, 0);
    launch_stream_t<false, false, float >(cat2, fc2T, fc_b2, t2,   TN, D2, DD, 0);
    ln_res_t_kernel<<<TN, 128>>>(h1, t2, ln2_g, ln2_b, h2t);
    gemm_kernel<true, float><<<dim3(2, 4, SPLITK), 256, SMEM_BATCH>>>(
        h2t, epwT, nullptr, part, NPTS, TD, DD, 0, 0, 0);
    splitk_reduce_kernel<<<(NPTS * DD + 255) / 256, 256>>>(part, ep_b, y, NPTS * DD, SPLITK, DD);
    for (int i = 0; i < 3; i++) {
        launch_stream_t<true,  false, __half>(y,  enc1T + (long)i * D2 * DD,
                                              enc_b1 + (long)i * D2, yh, NPTS, DD, D2, 0);
        launch_stream_t<false, true,  __half>(yh, enc2T + (long)i * DD * D2,
                                              enc_b2 + (long)i * DD, y,  NPTS, D2, DD, 0);
    }
    launch_stream_t<false, false, float>(y, outwT, out_b, out, NPTS, DD, TT, 0);
}

// round 15
// speedup vs baseline: 1.3281x; 1.0640x over previous
#include <cuda_runtime.h>
#include <cuda_fp16.h>
#include <math.h>

#define TT   365
#define NPTS 400
#define DD   104
#define HH   4
#define HD   26
#define TN   (TT*NPTS)      // 146000
#define D2   (2*DD)         // 208
#define D3   (3*DD)         // 312
#define TD   (TT*DD)        // 37960
#define SPLITK 40
#define KCHUNK 960
#define SMA  40              // A/B smem row stride in halves (32 k + 8 pad)
#define A_STH (128*SMA)
#define B_STH (64*SMA)
#define SMEM_BATCH ((3*A_STH + 3*B_STH)*2)
#define SMEM_STREAM_MAX 61440

// ---------------- scratch (device globals; no runtime allocation) -------------
__device__ __align__(16) __half g_hcat[(size_t)TN*DD];
__device__ __align__(16) __half g_h   [(size_t)TN*DD];
__device__ __align__(16) __half g_hT  [(size_t)TN*DD];   // [T][D][N]
__device__ __align__(16) __half g_graph[(size_t)TT*NPTS*NPTS];
__device__ __align__(16) __half g_z1  [(size_t)TN*DD];
__device__ __align__(16) __half g_qkv [(size_t)TN*D3];
__device__ __align__(16) __half g_qkv2[(size_t)TN*D3];
__device__ float g_kvs_s [(size_t)TT*HH*HD*HD];
__device__ float g_ksum_s[(size_t)TT*HH*HD];
__device__ float g_kvs_t [(size_t)NPTS*HH*HD*HD];
__device__ float g_ksum_t[(size_t)NPTS*HH*HD];
__device__ float g_kvs_s2 [(size_t)TT*HH*HD*HD];
__device__ float g_ksum_s2[(size_t)TT*HH*HD];
__device__ float g_kvs_t2 [(size_t)NPTS*HH*HD*HD];
__device__ float g_ksum_t2[(size_t)NPTS*HH*HD];
__device__ __align__(16) __half g_cat2 [(size_t)TN*D2];
__device__ __align__(16) __half g_cat2b[(size_t)TN*D2];
__device__ __align__(16) __half g_att0[(size_t)TN*DD];
__device__ float  g_att1[(size_t)TN*DD];
__device__ float  g_p0  [(size_t)TN*DD];
__device__ float  g_p1  [(size_t)TN*DD];
__device__ __align__(16) __half g_h1  [(size_t)TN*DD];
__device__ float  g_t2  [(size_t)TN*DD];
__device__ __align__(16) __half g_h2t [(size_t)NPTS*TD];
__device__ float  g_part[(size_t)SPLITK*NPTS*DD];
__device__ __align__(16) __half g_y   [(size_t)NPTS*DD];
__device__ __align__(16) __half g_yh  [(size_t)NPTS*D2];
__device__ __align__(16) __half g_wtsh[(size_t)16000000];

// offsets into g_wtsh (halves)
#define O_ADP   0L
#define O_WTP   11680000L
#define O_QKVW  11690816L
#define O_OPW   11755712L
#define O_PWW   11798976L
#define O_FC1   11820608L
#define O_FC2   11842240L
#define O_EPW   11863872L
#define O_ENC1  15811712L
#define O_ENC2  15876608L
#define O_OUTW  15941504L

// ---------------- cp.async issue helpers ----------------------------------------
__device__ __forceinline__ void issue_a(const __half* __restrict__ A, unsigned sAs,
                                        int bm, int k0, int kend, int M, long K, int tid)
{
    #pragma unroll
    for (int p = 0; p < 2; p++) {
        int idx = tid + p * 256;
        int m = idx >> 2, kq = (idx & 3) << 3;
        int gm = bm + m;
        int rem = kend - (k0 + kq);
        int sz = (gm < M && rem >= 8) ? 16 : 0;
        const __half* src = sz ? A + (long)gm * K + k0 + kq : A;
        unsigned dst = sAs + (unsigned)(m * SMA + kq) * 2u;
        asm volatile("cp.async.ca.shared.global [%0],[%1],16,%2;"
                     :: "r"(dst), "l"(src), "r"(sz));
    }
}

__device__ __forceinline__ void issue_b(const __half* __restrict__ B, unsigned sBs,
                                        int bn, int k0, int kend, int Nc, long K, int tid)
{
    int n = tid >> 2, kq = (tid & 3) << 3;
    int gn = bn + n;
    int rem = kend - (k0 + kq);
    int sz = (gn < Nc && rem >= 8) ? 16 : 0;
    const __half* src = sz ? B + (long)gn * K + k0 + kq : B;
    unsigned dst = sBs + (unsigned)(n * SMA + kq) * 2u;
    asm volatile("cp.async.ca.shared.global [%0],[%1],16,%2;"
                 :: "r"(dst), "l"(src), "r"(sz));
}

// ---------------- fp16 MMA on a k32 chunk ---------------------------------------
__device__ __forceinline__ void mma_chunk(const __half* __restrict__ As, int sbA,
                                          const __half* __restrict__ Bs, int sbB,
                                          int wm, int wn, int lane, float (*acc)[4][4])
{
    int r = lane >> 2, c2 = (lane & 3) << 1;
    #pragma unroll
    for (int ks = 0; ks < 2; ks++) {
        int k0 = ks * 16;
        unsigned a[2][4], b[4][2];
        #pragma unroll
        for (int mt = 0; mt < 2; mt++) {
            const __half* p = As + (wm * 32 + mt * 16 + r) * sbA + k0 + c2;
            a[mt][0] = *reinterpret_cast<const unsigned*>(p);
            a[mt][1] = *reinterpret_cast<const unsigned*>(p + 8 * sbA);
            a[mt][2] = *reinterpret_cast<const unsigned*>(p + 8);
            a[mt][3] = *reinterpret_cast<const unsigned*>(p + 8 * sbA + 8);
        }
        #pragma unroll
        for (int nt = 0; nt < 4; nt++) {
            const __half* q = Bs + (wn * 32 + nt * 8 + r) * sbB + k0 + c2;
            b[nt][0] = *reinterpret_cast<const unsigned*>(q);
            b[nt][1] = *reinterpret_cast<const unsigned*>(q + 8);
        }
        #pragma unroll
        for (int mt = 0; mt < 2; mt++)
            #pragma unroll
            for (int nt = 0; nt < 4; nt++)
                asm("mma.sync.aligned.m16n8k16.row.col.f32.f16.f16.f32 "
                    "{%0,%1,%2,%3},{%4,%5,%6,%7},{%8,%9},{%0,%1,%2,%3};"
                    : "+f"(acc[mt][nt][0]), "+f"(acc[mt][nt][1]),
                      "+f"(acc[mt][nt][2]), "+f"(acc[mt][nt][3])
                    : "r"(a[mt][0]), "r"(a[mt][1]), "r"(a[mt][2]), "r"(a[mt][3]),
                      "r"(b[nt][0]), "r"(b[nt][1]));
    }
}

// ---------------- epilogue (optional dual transposed write for h/hT) ------------
template<bool RELU, bool ACC, bool SPLIT, typename TC>
__device__ __forceinline__ void epilogue(float (*acc)[4][4], const float* bias,
                                         TC* __restrict__ C, int bm, int bn,
                                         int M, int Nc, int wm, int wn, int lane,
                                         __half* __restrict__ hT)
{
    int r = lane >> 2, c2 = (lane & 3) << 1;
    #pragma unroll
    for (int mt = 0; mt < 2; mt++) {
        #pragma unroll
        for (int nt = 0; nt < 4; nt++) {
            int gm0 = bm + wm * 32 + mt * 16 + r;
            int gn0 = bn + wn * 32 + nt * 8 + c2;
            #pragma unroll
            for (int hh = 0; hh < 2; hh++) {
                int gm = gm0 + hh * 8;
                if (gm >= M) continue;
                #pragma unroll
                for (int j = 0; j < 2; j++) {
                    int gn = gn0 + j;
                    if (gn >= Nc) continue;
                    float v = acc[mt][nt][hh * 2 + j];
                    if (!SPLIT && bias) v += bias[gn];
                    if (RELU) v = fmaxf(v, 0.f);
                    long ci = (long)gm * Nc + gn;
                    if (ACC) v += (float)C[ci];
                    C[ci] = (TC)v;
                    if (hT) {
                        int t = gm / NPTS, n = gm - t * NPTS;
                        hT[(long)t * DD * NPTS + (long)gn * NPTS + n] = __float2half_rn(v);
                    }
                }
            }
        }
    }
}

// ---------------- batched / split fp16 GEMM (B always [n][k]) -------------------
template<bool SPLIT, typename TC>
__global__ void __launch_bounds__(256)
gemm_kernel(const __half* __restrict__ A, const __half* __restrict__ B,
            const float* __restrict__ bias, TC* __restrict__ C,
            int M, int K, int Nc, long sA, long sB_, long sC)
{
    extern __shared__ __half dsmh[];
    int tid = threadIdx.x;
    int bm = blockIdx.y * 128, bn = blockIdx.x * 64;
    int kbeg = 0, kend = K;
    if (SPLIT) {
        int z = blockIdx.z;
        kbeg = z * KCHUNK;
        kend = min(K, kbeg + KCHUNK);
        C += (long)z * M * Nc;
    } else {
        int z = blockIdx.z;
        A += z * sA; B += z * sB_; C += z * sC;
    }
    int w = tid >> 5, lane = tid & 31;
    int wm = w >> 1, wn = w & 1;
    float acc[2][4][4];
    #pragma unroll
    for (int mt = 0; mt < 2; mt++)
        #pragma unroll
        for (int nt = 0; nt < 4; nt++)
            #pragma unroll
            for (int q = 0; q < 4; q++) acc[mt][nt][q] = 0.f;

    unsigned sbase = (unsigned)__cvta_generic_to_shared(dsmh);
    unsigned sA0 = sbase;
    unsigned sB0 = sbase + 3u * A_STH * 2u;

    int nk = (kend - kbeg + 31) >> 5;
    issue_a(A, sA0, bm, kbeg, kend, M, K, tid);
    issue_b(B, sB0, bn, kbeg, kend, Nc, K, tid);
    asm volatile("cp.async.commit_group;" ::: "memory");
    issue_a(A, sA0 + A_STH * 2u, bm, kbeg + 32, kend, M, K, tid);
    issue_b(B, sB0 + B_STH * 2u, bn, kbeg + 32, kend, Nc, K, tid);
    asm volatile("cp.async.commit_group;" ::: "memory");

    for (int it = 0; it < nk; it++) {
        asm volatile("cp.async.wait_group 1;" ::: "memory");
        __syncthreads();
        int s2 = (it + 2) % 3;
        int kn = kbeg + (it + 2) * 32;
        issue_a(A, sA0 + (unsigned)s2 * A_STH * 2u, bm, kn, kend, M, K, tid);
        issue_b(B, sB0 + (unsigned)s2 * B_STH * 2u, bn, kn, kend, Nc, K, tid);
        asm volatile("cp.async.commit_group;" ::: "memory");
        int sc = it % 3;
        mma_chunk(dsmh + sc * A_STH, SMA, dsmh + 3 * A_STH + sc * B_STH, SMA,
                  wm, wn, lane, acc);
    }
    epilogue<false, false, SPLIT, TC>(acc, bias, C, bm, bn, M, Nc, wm, wn, lane, nullptr);
}

// ---------------- persistent-B streaming GEMM (NN, non-batched) -----------------
template<bool RELU, bool ACC, typename TC>
__global__ void __launch_bounds__(256)
gemm_stream(const __half* __restrict__ A, const __half* __restrict__ Bt,
            const float* __restrict__ bias, TC* __restrict__ C,
            int M, int K, int Nc, int KP, __half* __restrict__ hTout)
{
    extern __shared__ __half dsmh[];
    __half* Asm = dsmh;
    __half* Bsm = dsmh + 3 * A_STH;
    int tid = threadIdx.x;
    int bn = blockIdx.x * 64;
    int nkc = (K + 31) >> 5;
    int KP32 = nkc * 32;
    int MT = (M + 127) >> 7;
    int w = tid >> 5, lane = tid & 31;
    int wm = w >> 1, wn = w & 1;

    unsigned sbase = (unsigned)__cvta_generic_to_shared(dsmh);
    unsigned sA0 = sbase;
    unsigned sB0 = sbase + 3u * A_STH * 2u;

    int nchunk = KP32 >> 3;
    for (int e = tid; e < 64 * nchunk; e += 256) {
        int n = e / nchunk, kc8 = e - n * nchunk;
        int k = kc8 << 3;
        int gn = bn + n;
        int sz = (gn < Nc && k < K) ? 16 : 0;
        const __half* src = sz ? Bt + (long)gn * K + k : Bt;
        unsigned dst = sB0 + (unsigned)(n * KP + k) * 2u;
        asm volatile("cp.async.ca.shared.global [%0],[%1],16,%2;"
                     :: "r"(dst), "l"(src), "r"(sz));
    }

    int mt_i = blockIdx.y;
    int kc_i = 0;
    if (mt_i < MT) issue_a(A, sA0, mt_i * 128, 0, K, M, K, tid);
    asm volatile("cp.async.commit_group;" ::: "memory");
    if (++kc_i == nkc) { kc_i = 0; mt_i += gridDim.y; }
    if (mt_i < MT) issue_a(A, sA0 + A_STH * 2u, mt_i * 128, kc_i * 32, K, M, K, tid);
    asm volatile("cp.async.commit_group;" ::: "memory");
    if (++kc_i == nkc) { kc_i = 0; mt_i += gridDim.y; }

    float acc[2][4][4];
    int stage = 0;
    for (int mt = blockIdx.y; mt < MT; mt += gridDim.y) {
        #pragma unroll
        for (int mtt = 0; mtt < 2; mtt++)
            #pragma unroll
            for (int nt = 0; nt < 4; nt++)
                #pragma unroll
                for (int q = 0; q < 4; q++) acc[mtt][nt][q] = 0.f;
        for (int kc = 0; kc < nkc; kc++) {
            asm volatile("cp.async.wait_group 1;" ::: "memory");
            __syncthreads();
            int s2 = (stage + 2) % 3;
            if (mt_i < MT) issue_a(A, sA0 + (unsigned)s2 * A_STH * 2u,
                                   mt_i * 128, kc_i * 32, K, M, K, tid);
            asm volatile("cp.async.commit_group;" ::: "memory");
            if (++kc_i == nkc) { kc_i = 0; mt_i += gridDim.y; }
            mma_chunk(Asm + stage * A_STH, SMA, Bsm + kc * 32, KP, wm, wn, lane, acc);
            stage = (stage + 1) % 3;
        }
        epilogue<RELU, ACC, false, TC>(acc, bias, C, mt * 128, bn, M, Nc, wm, wn, lane, hTout);
    }
}

// ---------------- fused relu-softmax normalize (fp16 in/out) --------------------
__global__ void normgraph_kernel(__half* __restrict__ g)
{
    long row = (long)blockIdx.x * 8 + (threadIdx.x >> 5);
    if (row >= (long)TN) return;
    int lane = threadIdx.x & 31;
    uint4* p = reinterpret_cast<uint4*>(g + row * NPTS);
    float v[2][8]; uint4 u;
    float m = 0.f;
    #pragma unroll
    for (int rch = 0; rch < 2; rch++) {
        int c = lane + rch * 32;
        if (c < 50) {
            u = p[c];
            const __half2* hp = reinterpret_cast<const __half2*>(&u);
            #pragma unroll
            for (int j = 0; j < 4; j++) {
                float2 f = __half22float2(hp[j]);
                v[rch][2 * j] = f.x; v[rch][2 * j + 1] = f.y;
                m = fmaxf(m, fmaxf(f.x, f.y));
            }
        }
    }
    #pragma unroll
    for (int o = 16; o > 0; o >>= 1) m = fmaxf(m, __shfl_xor_sync(~0u, m, o));
    float s = 0.f;
    #pragma unroll
    for (int rch = 0; rch < 2; rch++) {
        int c = lane + rch * 32;
        if (c < 50) {
            #pragma unroll
            for (int j = 0; j < 8; j++) {
                float e = __expf(fmaxf(v[rch][j], 0.f) - m);
                v[rch][j] = e; s += e;
            }
        }
    }
    #pragma unroll
    for (int o = 16; o > 0; o >>= 1) s += __shfl_xor_sync(~0u, s, o);
    float inv = 1.f / s;
    #pragma unroll
    for (int rch = 0; rch < 2; rch++) {
        int c = lane + rch * 32;
        if (c < 50) {
            uint4 ou;
            __half2* hp = reinterpret_cast<__half2*>(&ou);
            #pragma unroll
            for (int j = 0; j < 4; j++)
                hp[j] = __floats2half2_rn(v[rch][2 * j] * inv, v[rch][2 * j + 1] * inv);
            p[c] = ou;
        }
    }
}

// ---------------- weight conversion kernels -------------------------------------
__global__ void rnd2h_kernel(const float* __restrict__ src, __half* __restrict__ dst, long n2)
{
    long i = (long)blockIdx.x * 256 + threadIdx.x;
    if (i >= n2) return;
    float2 f = reinterpret_cast<const float2*>(src)[i];
    reinterpret_cast<__half2*>(dst)[i] = __floats2half2_rn(f.x, f.y);
}

__global__ void trnd_kernel(const float* __restrict__ src, __half* __restrict__ dst,
                            int K, int Nc)
{
    long j = (long)blockIdx.x * 256 + threadIdx.x;
    if (j >= (long)K * Nc) return;
    int n = (int)(j / K); long k = j - (long)n * K;
    dst[j] = __float2half_rn(src[k * Nc + n]);
}

__global__ void trnd_tiled_kernel(const float* __restrict__ src, __half* __restrict__ dst,
                                  int K, int Nc)
{
    __shared__ float tile[32][33];
    int k0 = blockIdx.x * 32, n0 = blockIdx.y * 32;
    int tx = threadIdx.x & 31, ty = threadIdx.x >> 5;
    #pragma unroll
    for (int i = ty; i < 32; i += 8) {
        int k = k0 + i, n = n0 + tx;
        tile[i][tx] = (k < K && n < Nc) ? src[(long)k * Nc + n] : 0.f;
    }
    __syncthreads();
    #pragma unroll
    for (int i = ty; i < 32; i += 8) {
        int n = n0 + i, k = k0 + tx;
        if (n < Nc && k < K) dst[(long)n * K + k] = __float2half_rn(tile[tx][i]);
    }
}

// ---------------- input proj + concat adaptive embedding ------------------------
__global__ void hcat_kernel(const float* __restrict__ x, const float* __restrict__ W_in,
                            const float* __restrict__ b_in, const __half* __restrict__ adp_h,
                            __half* __restrict__ hcat)
{
    long idx = (long)blockIdx.x * 256 + threadIdx.x;
    if (idx >= (long)TN * DD) return;
    long tn = idx / DD; int j = (int)(idx - tn * DD);
    int t = (int)(tn / NPTS), n = (int)(tn - (long)t * NPTS);
    __half v;
    if (j < 24) {
        const float* xr = x + ((long)n * TT + t) * 3;
        v = __float2half_rn(b_in[j] + xr[0] * W_in[0 * 24 + j]
                            + xr[1] * W_in[1 * 24 + j] + xr[2] * W_in[2 * 24 + j]);
    } else {
        v = adp_h[tn * 80 + (j - 24)];
    }
    hcat[idx] = v;
}

// ---------------- linear attention: both kvs orientations in one launch ---------
__global__ void kvs_dual_kernel(const __half* __restrict__ qkv,
                                float* __restrict__ kvs_s, float* __restrict__ ksum_s,
                                float* __restrict__ kvs_t, float* __restrict__ ksum_t)
{
    int b = blockIdx.x, h = blockIdx.y;
    long sB, sL; int L;
    float *kvs, *ksum;
    if (b < TT) {
        sB = (long)NPTS * D3; sL = D3; L = NPTS; kvs = kvs_s; ksum = ksum_s;
    } else {
        b -= TT;
        sB = D3; sL = (long)NPTS * D3; L = TT; kvs = kvs_t; ksum = ksum_t;
    }
    int w = threadIdx.x >> 5, lane = threadIdx.x & 31;
    int chunk = (L + 7) >> 3;
    int l0 = w * chunk, l1 = min(L, l0 + chunk);
    const __half* base = qkv + (long)b * sB + h * HD;
    float acc[HD];
    #pragma unroll
    for (int m = 0; m < HD; m++) acc[m] = 0.f;
    float accs = 0.f;
    for (int l = l0; l < l1; l++) {
        const __half* row = base + (long)l * sL;
        float kk = (lane < HD) ? __half2float(row[DD + lane]) : 0.f;
        float vv = (lane < HD) ? __half2float(row[2 * DD + lane]) : 0.f;
        float ss = kk * kk;
        #pragma unroll
        for (int o = 16; o > 0; o >>= 1) ss += __shfl_xor_sync(~0u, ss, o);
        float inv = 1.f / fmaxf(sqrtf(ss), 1e-12f);
        float kin = kk * inv;
        accs += kin;
        #pragma unroll
        for (int m = 0; m < HD; m++) {
            float km = __shfl_sync(~0u, kin, m);
            acc[m] += km * vv;
        }
    }
    __shared__ float red[8][HD][HD + 2];
    __shared__ float redk[8][32];
    if (lane < HD) {
        #pragma unroll
        for (int m = 0; m < HD; m++) red[w][m][lane] = acc[m];
    }
    redk[w][lane] = accs;
    __syncthreads();
    long basec = ((long)b * HH + h);
    for (int cell = threadIdx.x; cell < HD * HD; cell += 256) {
        int m = cell / HD, d = cell - m * HD;
        float s = 0.f;
        #pragma unroll
        for (int ww = 0; ww < 8; ww++) s += red[ww][m][d];
        kvs[basec * (HD * HD) + cell] = s;
    }
    if (threadIdx.x < HD) {
        float s = 0.f;
        #pragma unroll
        for (int ww = 0; ww < 8; ww++) s += redk[ww][threadIdx.x];
        ksum[basec * HD + threadIdx.x] = s;
    }
}

// ---------------- fused spatial+temporal attention output -----------------------
__global__ void attnout2_kernel(const __half* __restrict__ qkv,
                                const float* __restrict__ kvs_s, const float* __restrict__ ksum_s,
                                const float* __restrict__ kvs_t, const float* __restrict__ ksum_t,
                                __half* __restrict__ cat2)
{
    int n = blockIdx.x, t = blockIdx.y;
    int tid = threadIdx.x;
    long tok = (long)t * NPTS + n;
    const __half* row = qkv + tok * D3;
    __shared__ float sq[DD], sv[DD], sinv[HH], sden_s[HH], sden_t[HH];
    if (tid < DD) {
        sq[tid] = __half2float(row[tid]);
        sv[tid] = __half2float(row[2 * DD + tid]);
    }
    __syncthreads();
    if (tid < HH) {
        const float* qh = sq + tid * HD;
        float ss = 0.f;
        #pragma unroll
        for (int m = 0; m < HD; m++) ss += qh[m] * qh[m];
        float inv = 1.f / fmaxf(sqrtf(ss), 1e-12f);
        sinv[tid] = inv;
        const float* ks = ksum_s + ((long)t * HH + tid) * HD;
        const float* kt = ksum_t + ((long)n * HH + tid) * HD;
        float ds = 0.f, dt = 0.f;
        #pragma unroll
        for (int m = 0; m < HD; m++) { ds += qh[m] * ks[m]; dt += qh[m] * kt[m]; }
        sden_s[tid] = ds * inv + (float)NPTS;
        sden_t[tid] = dt * inv + (float)TT;
    }
    __syncthreads();
    if (tid < DD) {
        int h = tid / HD, d = tid - h * HD;
        const float* qh = sq + h * HD;
        const float* kv_s = kvs_s + ((long)t * HH + h) * (HD * HD) + d;
        const float* kv_t = kvs_t + ((long)n * HH + h) * (HD * HD) + d;
        float ss = 0.f, st = 0.f;
        #pragma unroll
        for (int m = 0; m < HD; m++) {
            ss += qh[m] * kv_s[m * HD];
            st += qh[m] * kv_t[m * HD];
        }
        float inv = sinv[h], vv = sv[tid];
        cat2[tok * D2 + tid]      = __float2half_rn((ss * inv + (float)NPTS * vv) / sden_s[h]);
        cat2[tok * D2 + DD + tid] = __float2half_rn((st * inv + (float)TT   * vv) / sden_t[h]);
    }
}

// ---------------- fused combine + LayerNorm --------------------------------------
__global__ void combine_ln_kernel(const __half* __restrict__ h, const __half* __restrict__ a0,
                                  const float* __restrict__ a1, const float* __restrict__ p0,
                                  const float* __restrict__ p1, const float* __restrict__ gam,
                                  const float* __restrict__ bet, __half* __restrict__ out)
{
    long row = blockIdx.x; int tid = threadIdx.x;
    __shared__ float red[4];
    long i = row * DD + tid;
    float v = 0.f;
    if (tid < DD)
        v = 2.f * (__half2float(h[i]) + __half2float(a0[i]) * p0[i] + 0.01f * a1[i] * p1[i]);
    float s = (tid < DD) ? v : 0.f;
    #pragma unroll
    for (int o = 16; o > 0; o >>= 1) s += __shfl_xor_sync(~0u, s, o);
    if ((tid & 31) == 0) red[tid >> 5] = s;
    __syncthreads();
    float mean = (red[0] + red[1] + red[2] + red[3]) / (float)DD;
    __syncthreads();
    float d = (tid < DD) ? (v - mean) : 0.f;
    float s2 = d * d;
    #pragma unroll
    for (int o = 16; o > 0; o >>= 1) s2 += __shfl_xor_sync(~0u, s2, o);
    if ((tid & 31) == 0) red[tid >> 5] = s2;
    __syncthreads();
    float var = (red[0] + red[1] + red[2] + red[3]) / (float)DD;
    if (tid < DD) out[i] = __float2half_rn(d * rsqrtf(var + 1e-5f) * gam[tid] + bet[tid]);
}

// ln + residual, writing DIRECTLY into transposed layout h2t[n][t*DD+d]
__global__ void ln_res_t_kernel(const __half* __restrict__ a, const float* __restrict__ b,
                                const float* __restrict__ gam, const float* __restrict__ bet,
                                __half* __restrict__ h2t)
{
    long row = blockIdx.x; int tid = threadIdx.x;
    __shared__ float red[4];
    long i = row * DD + tid;
    float v = 0.f;
    if (tid < DD) v = __half2float(a[i]) + b[i];
    float s = (tid < DD) ? v : 0.f;
    #pragma unroll
    for (int o = 16; o > 0; o >>= 1) s += __shfl_xor_sync(~0u, s, o);
    if ((tid & 31) == 0) red[tid >> 5] = s;
    __syncthreads();
    float mean = (red[0] + red[1] + red[2] + red[3]) / (float)DD;
    __syncthreads();
    float d = (tid < DD) ? (v - mean) : 0.f;
    float s2 = d * d;
    #pragma unroll
    for (int o = 16; o > 0; o >>= 1) s2 += __shfl_xor_sync(~0u, s2, o);
    if ((tid & 31) == 0) red[tid >> 5] = s2;
    __syncthreads();
    float var = (red[0] + red[1] + red[2] + red[3]) / (float)DD;
    if (tid < DD) {
        long t = row / NPTS, n = row - t * NPTS;
        h2t[n * (long)TD + t * DD + tid] =
            __float2half_rn(d * rsqrtf(var + 1e-5f) * gam[tid] + bet[tid]);
    }
}

// ---------------- split-K deterministic reduction -------------------------------
__global__ void splitk_reduce_kernel(const float* __restrict__ part, const float* __restrict__ bias,
                                     __half* __restrict__ y, int MN, int Z, int Nc)
{
    int i = blockIdx.x * 256 + threadIdx.x;
    if (i >= MN) return;
    float s = bias[i % Nc];
    for (int z = 0; z < Z; z++) s += part[(long)z * MN + i];
    y[i] = __float2half_rn(s);
}

// ---------------- streaming GEMM launcher ---------------------------------------
template<bool RELU, bool ACC, typename TC>
static void launch_stream_t(const __half* A, const __half* Bt, const float* bias, TC* C,
                            int M, int K, int Nc, cudaStream_t st, __half* hT = nullptr)
{
    int nkc = (K + 31) / 32;
    int KP = nkc * 32 + 8;
    int smem = 3 * A_STH * 2 + 64 * KP * 2;
    int nx = (Nc + 63) / 64;
    int MT = (M + 127) / 128;
    int bps = 232448 / smem;             // blocks per SM by smem
    if (bps < 1) bps = 1;
    if (bps > 5) bps = 5;
    int gy = (148 * bps + nx - 1) / nx;
    if (gy > MT) gy = MT;
    gemm_stream<RELU, ACC, TC><<<dim3(nx, gy), 256, smem, st>>>(A, Bt, bias, C, M, K, Nc, KP, hT);
}

// ---------------- host orchestration --------------------------------------------
static void run_attention(const __half* x4, const __half* qwT, const __half* owT,
                          const float* ob, __half* qkv,
                          float* kvs_s, float* ksum_s, float* kvs_t, float* ksum_t,
                          __half* cat2, __half* att_h, float* att_f, cudaStream_t st)
{
    launch_stream_t<false, false, __half>(x4, qwT, nullptr, qkv, TN, DD, D3, st);
    kvs_dual_kernel<<<dim3(TT + NPTS, HH), 256, 0, st>>>(qkv, kvs_s, ksum_s, kvs_t, ksum_t);
    attnout2_kernel<<<dim3(NPTS, TT), 128, 0, st>>>(qkv, kvs_s, ksum_s, kvs_t, ksum_t, cat2);
    if (att_h) launch_stream_t<false, false, __half>(cat2, owT, ob, att_h, TN, D2, DD, st);
    else       launch_stream_t<false, false, float >(cat2, owT, ob, att_f, TN, D2, DD, st);
}

extern "C" void kernel_launch(void* const* d_in, const int* in_sizes, int n_in,
                              void* d_out, int out_size)
{
    (void)in_sizes; (void)n_in; (void)out_size;
    const float* x     = (const float*)d_in[0];
    const float* W_in  = (const float*)d_in[1];
    const float* b_in  = (const float*)d_in[2];
    const float* adp   = (const float*)d_in[3];
    const float* W_tp  = (const float*)d_in[4];
    const float* b_tp  = (const float*)d_in[5];
    const float* qkv_w = (const float*)d_in[6];
    const float* op_w  = (const float*)d_in[7];
    const float* op_b  = (const float*)d_in[8];
    const float* pw_w  = (const float*)d_in[9];
    const float* pw_b  = (const float*)d_in[10];
    const float* fc_w1 = (const float*)d_in[11];
    const float* fc_b1 = (const float*)d_in[12];
    const float* fc_w2 = (const float*)d_in[13];
    const float* fc_b2 = (const float*)d_in[14];
    const float* ln1_g = (const float*)d_in[15];
    const float* ln1_b = (const float*)d_in[16];
    const float* ln2_g = (const float*)d_in[17];
    const float* ln2_b = (const float*)d_in[18];
    const float* ep_w  = (const float*)d_in[19];
    const float* ep_b  = (const float*)d_in[20];
    const float* enc_w1= (const float*)d_in[21];
    const float* enc_b1= (const float*)d_in[22];
    const float* enc_w2= (const float*)d_in[23];
    const float* enc_b2= (const float*)d_in[24];
    const float* out_w = (const float*)d_in[25];
    const float* out_b = (const float*)d_in[26];
    float* out = (float*)d_out;

    static cudaStream_t s1 = nullptr, s2 = nullptr;
    static cudaEvent_t evF, evAdp, evHT, evB1, evW;
    if (!s1) {
        cudaStreamCreateWithFlags(&s1, cudaStreamNonBlocking);
        cudaStreamCreateWithFlags(&s2, cudaStreamNonBlocking);
        cudaEventCreateWithFlags(&evF,   cudaEventDisableTiming);
        cudaEventCreateWithFlags(&evAdp, cudaEventDisableTiming);
        cudaEventCreateWithFlags(&evHT,  cudaEventDisableTiming);
        cudaEventCreateWithFlags(&evB1,  cudaEventDisableTiming);
        cudaEventCreateWithFlags(&evW,   cudaEventDisableTiming);
        cudaFuncSetAttribute(gemm_kernel<false, __half>,
                             cudaFuncAttributeMaxDynamicSharedMemorySize, SMEM_BATCH);
        cudaFuncSetAttribute(gemm_kernel<true, float>,
                             cudaFuncAttributeMaxDynamicSharedMemorySize, SMEM_BATCH);
        cudaFuncSetAttribute(gemm_stream<false, false, __half>,
                             cudaFuncAttributeMaxDynamicSharedMemorySize, SMEM_STREAM_MAX);
        cudaFuncSetAttribute(gemm_stream<true, false, __half>,
                             cudaFuncAttributeMaxDynamicSharedMemorySize, SMEM_STREAM_MAX);
        cudaFuncSetAttribute(gemm_stream<false, true, __half>,
                             cudaFuncAttributeMaxDynamicSharedMemorySize, SMEM_STREAM_MAX);
        cudaFuncSetAttribute(gemm_stream<false, false, float>,
                             cudaFuncAttributeMaxDynamicSharedMemorySize, SMEM_STREAM_MAX);
    }

    __half *hcat, *h, *hT, *graph, *z1, *qkv, *qkv2, *cat2, *cat2b, *att0;
    __half *h1, *h2t, *y, *yh, *wtsh;
    float *kvs_s, *ksum_s, *kvs_t, *ksum_t, *kvs_s2, *ksum_s2, *kvs_t2, *ksum_t2;
    float *att1, *p0, *p1, *t2, *part;
    cudaGetSymbolAddress((void**)&hcat, g_hcat);
    cudaGetSymbolAddress((void**)&h,    g_h);
    cudaGetSymbolAddress((void**)&hT,   g_hT);
    cudaGetSymbolAddress((void**)&graph,g_graph);
    cudaGetSymbolAddress((void**)&z1,   g_z1);
    cudaGetSymbolAddress((void**)&qkv,  g_qkv);
    cudaGetSymbolAddress((void**)&qkv2, g_qkv2);
    cudaGetSymbolAddress((void**)&kvs_s,  g_kvs_s);
    cudaGetSymbolAddress((void**)&ksum_s, g_ksum_s);
    cudaGetSymbolAddress((void**)&kvs_t,  g_kvs_t);
    cudaGetSymbolAddress((void**)&ksum_t, g_ksum_t);
    cudaGetSymbolAddress((void**)&kvs_s2, g_kvs_s2);
    cudaGetSymbolAddress((void**)&ksum_s2,g_ksum_s2);
    cudaGetSymbolAddress((void**)&kvs_t2, g_kvs_t2);
    cudaGetSymbolAddress((void**)&ksum_t2,g_ksum_t2);
    cudaGetSymbolAddress((void**)&cat2,  g_cat2);
    cudaGetSymbolAddress((void**)&cat2b, g_cat2b);
    cudaGetSymbolAddress((void**)&att0, g_att0);
    cudaGetSymbolAddress((void**)&att1, g_att1);
    cudaGetSymbolAddress((void**)&p0,   g_p0);
    cudaGetSymbolAddress((void**)&p1,   g_p1);
    cudaGetSymbolAddress((void**)&h1,   g_h1);
    cudaGetSymbolAddress((void**)&t2,   g_t2);
    cudaGetSymbolAddress((void**)&h2t,  g_h2t);
    cudaGetSymbolAddress((void**)&part, g_part);
    cudaGetSymbolAddress((void**)&y,    g_y);
    cudaGetSymbolAddress((void**)&yh,   g_yh);
    cudaGetSymbolAddress((void**)&wtsh, g_wtsh);

    __half* adp_h  = wtsh + O_ADP;
    __half* WtpT   = wtsh + O_WTP;
    __half* qkvwT  = wtsh + O_QKVW;
    __half* opwT   = wtsh + O_OPW;
    __half* pwwT   = wtsh + O_PWW;
    __half* fc1T   = wtsh + O_FC1;
    __half* fc2T   = wtsh + O_FC2;
    __half* epwT   = wtsh + O_EPW;
    __half* enc1T  = wtsh + O_ENC1;
    __half* enc2T  = wtsh + O_ENC2;
    __half* outwT  = wtsh + O_OUTW;

    // ======== FORK s2: all weight conversions off the critical path ========
    cudaEventRecord(evF, 0);
    cudaStreamWaitEvent(s2, evF, 0);
    #define TRND(src, dst, K_, N_) \
        trnd_kernel<<<(((long)(K_) * (N_)) + 255) / 256, 256, 0, s2>>>(src, dst, K_, N_)
    TRND(W_tp, WtpT, DD, DD);
    TRND(qkv_w,            qkvwT,             DD, D3);
    TRND(qkv_w + DD * D3,  qkvwT + D3 * DD,   DD, D3);
    TRND(op_w,             opwT,              D2, DD);
    TRND(op_w + D2 * DD,   opwT + DD * D2,    D2, DD);
    TRND(pw_w,             pwwT,              DD, DD);
    TRND(pw_w + DD * DD,   pwwT + DD * DD,    DD, DD);
    TRND(fc_w1, fc1T, DD, D2);
    TRND(fc_w2, fc2T, D2, DD);
    for (int i = 0; i < 3; i++) {
        TRND(enc_w1 + (long)i * DD * D2, enc1T + (long)i * D2 * DD, DD, D2);
        TRND(enc_w2 + (long)i * D2 * DD, enc2T + (long)i * DD * D2, D2, DD);
    }
    TRND(out_w, outwT, DD, TT);
    trnd_tiled_kernel<<<dim3((TD + 31) / 32, (DD + 31) / 32), 256, 0, s2>>>(ep_w, epwT, TD, DD);
    cudaEventRecord(evW, s2);

    // ---- main: adp conversion (graph branch + hcat need it) ----
    {
        long n2 = (long)TT * NPTS * 80 / 2;
        rnd2h_kernel<<<(n2 + 255) / 256, 256>>>(adp, adp_h, n2);
    }

    // ======== FORK s1: graph branch ========
    cudaEventRecord(evAdp, 0);
    cudaStreamWaitEvent(s1, evAdp, 0);
    gemm_kernel<false, __half><<<dim3(7, 4, TT), 256, SMEM_BATCH, s1>>>(
        adp_h, adp_h, nullptr, graph, NPTS, 80, NPTS,
        (long)NPTS * 80, (long)NPTS * 80, (long)NPTS * NPTS);
    normgraph_kernel<<<(TN + 7) / 8, 256, 0, s1>>>(graph);

    // ---- main: h chain; W_tp GEMM also emits hT (fused transpose) ----
    hcat_kernel<<<((long)TN * DD + 255) / 256, 256>>>(x, W_in, b_in, adp_h, hcat);
    cudaStreamWaitEvent(0, evW, 0);
    launch_stream_t<false, false, __half>(hcat, WtpT, b_tp, h, TN, DD, DD, 0, hT);
    cudaEventRecord(evHT, 0);

    // ======== s1: z1 + attention branch 1 ========
    cudaStreamWaitEvent(s1, evHT, 0);
    gemm_kernel<false, __half><<<dim3(2, 4, TT), 256, SMEM_BATCH, s1>>>(
        graph, hT, nullptr, z1, NPTS, NPTS, DD,
        (long)NPTS * NPTS, (long)DD * NPTS, (long)NPTS * DD);
    run_attention(z1, qkvwT + D3 * DD, opwT + DD * D2, op_b + DD, qkv2,
                  kvs_s2, ksum_s2, kvs_t2, ksum_t2, cat2b, nullptr, att1, s1);
    cudaEventRecord(evB1, s1);

    // ---- main (concurrent): p0, attention branch 0, p1 ----
    launch_stream_t<false, false, float>(h, pwwT, pw_b, p0, TN, DD, DD, 0);
    run_attention(h, qkvwT, opwT, op_b, qkv, kvs_s, ksum_s, kvs_t, ksum_t,
                  cat2, att0, nullptr, 0);
    launch_stream_t<false, false, float>(att0, pwwT + DD * DD, pw_b + DD, p1, TN, DD, DD, 0);

    // ======== JOIN ========
    cudaStreamWaitEvent(0, evB1, 0);

    combine_ln_kernel<<<TN, 128>>>(h, att0, att1, p0, p1, ln1_g, ln1_b, h1);
    launch_stream_t<true,  false, __half>(h1,   fc1T, fc_b1, cat2, TN, DD, D2, 0);
    launch_stream_t<false, false, float >(cat2, fc2T, fc_b2, t2,   TN, D2, DD, 0);
    ln_res_t_kernel<<<TN, 128>>>(h1, t2, ln2_g, ln2_b, h2t);
    gemm_kernel<true, float><<<dim3(2, 4, SPLITK), 256, SMEM_BATCH>>>(
        h2t, epwT, nullptr, part, NPTS, TD, DD, 0, 0, 0);
    splitk_reduce_kernel<<<(NPTS * DD + 255) / 256, 256>>>(part, ep_b, y, NPTS * DD, SPLITK, DD);
    for (int i = 0; i < 3; i++) {
        launch_stream_t<true,  false, __half>(y,  enc1T + (long)i * D2 * DD,
                                              enc_b1 + (long)i * D2, yh, NPTS, DD, D2, 0);
        launch_stream_t<false, true,  __half>(yh, enc2T + (long)i * DD * D2,
                                              enc_b2 + (long)i * DD, y,  NPTS, D2, DD, 0);
    }
    launch_stream_t<false, false, float>(y, outwT, out_b, out, NPTS, DD, TT, 0);
}